// round 2
// baseline (speedup 1.0000x reference)
#include <cuda_runtime.h>
#include <cuda_bf16.h>
#include <cstdint>

// ---------------------------------------------------------------------------
// Problem constants (EncoderGAT: 2-layer GAT, PyG-style, eval mode)
// ---------------------------------------------------------------------------
#define NN      20000     // nodes
#define EE      160000    // directed edges (before self-loops)
#define ETOT    (EE + NN) // edges + self-loops
#define IN_CH   128
#define H1      36        // heads layer 1
#define C1      36        // channels per head layer 1
#define HID     (H1 * C1) // 1296
#define OUT_CH  128

// ---------------------------------------------------------------------------
// Device scratch (static __device__ arrays; no dynamic allocation allowed)
// ---------------------------------------------------------------------------
__device__ __align__(16) float g_h1[(size_t)NN * HID];    // x @ W1          (103.7 MB)
__device__ __align__(16) float g_out1[(size_t)NN * HID];  // relu(agg1 + b1) (103.7 MB)
__device__ __align__(16) float g_h2[(size_t)NN * OUT_CH]; // out1 @ W2       (10.2 MB)
__device__ __align__(16) float g_as1[NN * H1];
__device__ __align__(16) float g_ad1[NN * H1];
__device__ __align__(16) float g_as2[NN];
__device__ __align__(16) float g_ad2[NN];
__device__ __align__(16) float g_e1[(size_t)ETOT * H1];   // edge logits layer 1
__device__ __align__(16) float g_e2[ETOT];                // layer 2
__device__ int   g_hist[NN];
__device__ int   g_rowptr[NN + 1];
__device__ int   g_cursor[NN];
__device__ int   g_srt_src[ETOT];               // CSR (by dst): src node per slot
__device__ int   g_srt_eid[ETOT];               // CSR: original edge id per slot

// ---------------------------------------------------------------------------
// Edge helpers: edges j < EE come from edge_index (int32!), j >= EE self-loops
// ---------------------------------------------------------------------------
__device__ __forceinline__ int edge_src(const int* __restrict__ ei, int j) {
    return (j < EE) ? ei[j] : (j - EE);
}
__device__ __forceinline__ int edge_dst(const int* __restrict__ ei, int j) {
    return (j < EE) ? ei[EE + j] : (j - EE);
}

// ---------------------------------------------------------------------------
// CSR build: histogram -> scan -> scatter
// ---------------------------------------------------------------------------
__global__ void zero_hist_kernel() {
    int i = blockIdx.x * blockDim.x + threadIdx.x;
    if (i < NN) g_hist[i] = 0;
}

__global__ void hist_kernel(const int* __restrict__ ei) {
    int j = blockIdx.x * blockDim.x + threadIdx.x;
    if (j < ETOT) atomicAdd(&g_hist[edge_dst(ei, j)], 1);
}

// single-block inclusive scan over NN bins (chunked Hillis-Steele)
__global__ void scan_kernel() {
    __shared__ int sdata[1024];
    int t = threadIdx.x;
    if (t == 0) g_rowptr[0] = 0;
    int offset = 0;
    for (int base = 0; base < NN; base += 1024) {
        int v = (base + t < NN) ? g_hist[base + t] : 0;
        sdata[t] = v;
        __syncthreads();
        for (int d = 1; d < 1024; d <<= 1) {
            int add = (t >= d) ? sdata[t - d] : 0;
            __syncthreads();
            sdata[t] += add;
            __syncthreads();
        }
        int incl = sdata[t];
        if (base + t < NN) {
            g_rowptr[base + t + 1] = offset + incl;
            g_cursor[base + t]     = offset + incl - v;   // exclusive
        }
        offset += sdata[1023];
        __syncthreads();
    }
}

__global__ void scatter_kernel(const int* __restrict__ ei) {
    int j = blockIdx.x * blockDim.x + threadIdx.x;
    if (j >= ETOT) return;
    int d = edge_dst(ei, j);
    int pos = atomicAdd(&g_cursor[d], 1);
    g_srt_src[pos] = edge_src(ei, j);
    g_srt_eid[pos] = j;
}

// ---------------------------------------------------------------------------
// Shared-memory tiled fp32 GEMM: C[M,N] = A[M,K] @ B[K,N]
// BM=BN=128, BK=16, 256 threads, 8x8 microtile per thread.
// Requires K % 16 == 0 (holds: 128 and 1296).
// ---------------------------------------------------------------------------
#define BM 128
#define BN 128
#define BK 16

__device__ __forceinline__ void gemm_body(const float* __restrict__ A,
                                          const float* __restrict__ B,
                                          float* __restrict__ C,
                                          int M, int N, int K) {
    __shared__ __align__(16) float As[BK][BM];   // A tile, k-major
    __shared__ __align__(16) float Bs[BK][BN];

    int tid = threadIdx.x;                  // 0..255
    int tx = tid & 15;                      // 16 thread-cols
    int ty = tid >> 4;                      // 16 thread-rows
    int row0 = blockIdx.y * BM;
    int col0 = blockIdx.x * BN;

    float acc[8][8] = {};

    for (int k0 = 0; k0 < K; k0 += BK) {
        // ---- load A tile: 128 rows x 16 k = 512 float4, 2 per thread ----
        #pragma unroll
        for (int l = 0; l < 2; l++) {
            int q  = tid + l * 256;
            int ar = q >> 2;                // 0..127 (m)
            int ac = (q & 3) * 4;           // 0,4,8,12 (k)
            float4 av = make_float4(0.f, 0.f, 0.f, 0.f);
            int am = row0 + ar;
            if (am < M)
                av = *(const float4*)&A[(size_t)am * K + k0 + ac];
            As[ac + 0][ar] = av.x;
            As[ac + 1][ar] = av.y;
            As[ac + 2][ar] = av.z;
            As[ac + 3][ar] = av.w;

            // ---- load B tile: 16 k x 128 n = 512 float4 ----
            int br = q >> 5;                // 0..15 (k)
            int bc = (q & 31) * 4;          // 0..124 (n)
            float4 bv = make_float4(0.f, 0.f, 0.f, 0.f);
            int bn = col0 + bc;
            const float* brow = &B[(size_t)(k0 + br) * N];
            if (bn + 3 < N) {
                bv = *(const float4*)&brow[bn];
            } else {
                if (bn + 0 < N) bv.x = brow[bn + 0];
                if (bn + 1 < N) bv.y = brow[bn + 1];
                if (bn + 2 < N) bv.z = brow[bn + 2];
                if (bn + 3 < N) bv.w = brow[bn + 3];
            }
            Bs[br][bc + 0] = bv.x;
            Bs[br][bc + 1] = bv.y;
            Bs[br][bc + 2] = bv.z;
            Bs[br][bc + 3] = bv.w;
        }
        __syncthreads();

        #pragma unroll
        for (int kk = 0; kk < BK; kk++) {
            float a[8], b[8];
            *(float4*)&a[0] = *(const float4*)&As[kk][ty * 8];
            *(float4*)&a[4] = *(const float4*)&As[kk][ty * 8 + 4];
            *(float4*)&b[0] = *(const float4*)&Bs[kk][tx * 8];
            *(float4*)&b[4] = *(const float4*)&Bs[kk][tx * 8 + 4];
            #pragma unroll
            for (int i = 0; i < 8; i++)
                #pragma unroll
                for (int j = 0; j < 8; j++)
                    acc[i][j] = fmaf(a[i], b[j], acc[i][j]);
        }
        __syncthreads();
    }

    // ---- store ----
    int cb = col0 + tx * 8;
    #pragma unroll
    for (int i = 0; i < 8; i++) {
        int r = row0 + ty * 8 + i;
        if (r >= M) continue;
        float* crow = &C[(size_t)r * N];
        if (cb + 3 < N) {
            *(float4*)&crow[cb] =
                make_float4(acc[i][0], acc[i][1], acc[i][2], acc[i][3]);
        } else {
            #pragma unroll
            for (int j = 0; j < 4; j++)
                if (cb + j < N) crow[cb + j] = acc[i][j];
        }
        if (cb + 7 < N) {
            *(float4*)&crow[cb + 4] =
                make_float4(acc[i][4], acc[i][5], acc[i][6], acc[i][7]);
        } else {
            #pragma unroll
            for (int j = 4; j < 8; j++)
                if (cb + j < N) crow[cb + j] = acc[i][j];
        }
    }
}

__global__ void __launch_bounds__(256)
gemm1_kernel(const float* __restrict__ x, const float* __restrict__ W1) {
    gemm_body(x, W1, g_h1, NN, HID, IN_CH);
}

__global__ void __launch_bounds__(256)
gemm2_kernel(const float* __restrict__ W2) {
    gemm_body(g_out1, W2, g_h2, NN, OUT_CH, HID);
}

// ---------------------------------------------------------------------------
// Attention coefficients
// ---------------------------------------------------------------------------
// Layer 1: as1[n,h] = sum_c h1[n, h*36+c] * a_src1[h*36+c]   (and ad1)
__global__ void attn1_kernel(const float* __restrict__ a_src,
                             const float* __restrict__ a_dst) {
    int n = blockIdx.x;
    __shared__ float row[HID];
    const float* hrow = &g_h1[(size_t)n * HID];
    for (int c = threadIdx.x; c < HID; c += blockDim.x) row[c] = hrow[c];
    __syncthreads();
    int t = threadIdx.x;
    if (t < 2 * H1) {
        int h = (t < H1) ? t : (t - H1);
        const float* a = (t < H1) ? a_src : a_dst;
        float s = 0.f;
        #pragma unroll
        for (int c = 0; c < C1; c++) s = fmaf(row[h * C1 + c], a[h * C1 + c], s);
        if (t < H1) g_as1[n * H1 + h] = s;
        else        g_ad1[n * H1 + h] = s;
    }
}

// Layer 2 (1 head, 128 ch): one warp per node
__global__ void attn2_kernel(const float* __restrict__ a_src,
                             const float* __restrict__ a_dst) {
    int warp = (blockIdx.x * blockDim.x + threadIdx.x) >> 5;
    int lane = threadIdx.x & 31;
    if (warp >= NN) return;
    const float* hrow = &g_h2[(size_t)warp * OUT_CH];
    float4 v  = *(const float4*)&hrow[lane * 4];
    float4 as = *(const float4*)&a_src[lane * 4];
    float4 ad = *(const float4*)&a_dst[lane * 4];
    float ss = v.x * as.x + v.y * as.y + v.z * as.z + v.w * as.w;
    float sd = v.x * ad.x + v.y * ad.y + v.z * ad.z + v.w * ad.w;
    #pragma unroll
    for (int o = 16; o; o >>= 1) {
        ss += __shfl_xor_sync(0xFFFFFFFFu, ss, o);
        sd += __shfl_xor_sync(0xFFFFFFFFu, sd, o);
    }
    if (lane == 0) { g_as2[warp] = ss; g_ad2[warp] = sd; }
}

// ---------------------------------------------------------------------------
// Per-edge raw attention logits (leaky relu, slope 0.2)
// ---------------------------------------------------------------------------
__global__ void edge1_kernel(const int* __restrict__ ei) {
    int idx = blockIdx.x * blockDim.x + threadIdx.x;
    if (idx >= ETOT * H1) return;
    int e = idx / H1;
    int h = idx - e * H1;
    int s = edge_src(ei, e);
    int d = edge_dst(ei, e);
    float v = g_as1[s * H1 + h] + g_ad1[d * H1 + h];
    g_e1[idx] = (v > 0.f) ? v : 0.2f * v;
}

__global__ void edge2_kernel(const int* __restrict__ ei) {
    int e = blockIdx.x * blockDim.x + threadIdx.x;
    if (e >= ETOT) return;
    int s = edge_src(ei, e);
    int d = edge_dst(ei, e);
    float v = g_as2[s] + g_ad2[d];
    g_e2[e] = (v > 0.f) ? v : 0.2f * v;
}

// ---------------------------------------------------------------------------
// Layer-1 aggregation: per-dst softmax over in-edges + weighted sum of h1[src]
// One block (448 threads) per node. Thread t owns channels t, t+448, t+896.
// ---------------------------------------------------------------------------
#define AGG1_THREADS 448
__global__ void __launch_bounds__(AGG1_THREADS)
agg1_kernel(const float* __restrict__ bias) {
    int n = blockIdx.x;
    int t = threadIdx.x;
    __shared__ float sm_m[H1];
    __shared__ float sm_inv[H1];

    int beg = g_rowptr[n];
    int end = g_rowptr[n + 1];

    if (t < H1) {
        float m = -1e30f;
        for (int j = beg; j < end; j++)
            m = fmaxf(m, g_e1[(size_t)g_srt_eid[j] * H1 + t]);
        float s = 0.f;
        for (int j = beg; j < end; j++)
            s += __expf(g_e1[(size_t)g_srt_eid[j] * H1 + t] - m);
        sm_m[t]   = m;
        sm_inv[t] = 1.0f / (s + 1e-16f);
    }
    __syncthreads();

    int c0 = t, c1 = t + AGG1_THREADS, c2 = t + 2 * AGG1_THREADS;
    int h0 = c0 / C1, h1h = c1 / C1, h2h = (c2 < HID) ? (c2 / C1) : 0;
    float m0 = sm_m[h0],  i0 = sm_inv[h0];
    float m1 = sm_m[h1h], i1 = sm_inv[h1h];
    float m2 = (c2 < HID) ? sm_m[h2h]   : 0.f;
    float i2 = (c2 < HID) ? sm_inv[h2h] : 0.f;

    float acc0 = 0.f, acc1 = 0.f, acc2 = 0.f;
    for (int j = beg; j < end; j++) {
        int src = g_srt_src[j];
        int eid = g_srt_eid[j];
        const float* hrow = &g_h1[(size_t)src * HID];
        const float* erow = &g_e1[(size_t)eid * H1];
        float w0 = __expf(erow[h0]  - m0) * i0;
        float w1 = __expf(erow[h1h] - m1) * i1;
        acc0 = fmaf(hrow[c0], w0, acc0);
        acc1 = fmaf(hrow[c1], w1, acc1);
        if (c2 < HID) {
            float w2 = __expf(erow[h2h] - m2) * i2;
            acc2 = fmaf(hrow[c2], w2, acc2);
        }
    }

    float* orow = &g_out1[(size_t)n * HID];
    float v0 = acc0 + bias[c0];
    orow[c0] = (v0 > 0.f) ? v0 : 0.f;
    float v1 = acc1 + bias[c1];
    orow[c1] = (v1 > 0.f) ? v1 : 0.f;
    if (c2 < HID) {
        float v2 = acc2 + bias[c2];
        orow[c2] = (v2 > 0.f) ? v2 : 0.f;
    }
}

// ---------------------------------------------------------------------------
// Layer-2 aggregation (1 head, 128 channels) -> final output with bias + relu
// ---------------------------------------------------------------------------
__global__ void __launch_bounds__(OUT_CH)
agg2_kernel(const float* __restrict__ bias, float* __restrict__ out) {
    int n = blockIdx.x;
    int t = threadIdx.x;
    __shared__ float sm_m, sm_inv;

    int beg = g_rowptr[n];
    int end = g_rowptr[n + 1];

    if (t == 0) {
        float m = -1e30f;
        for (int j = beg; j < end; j++)
            m = fmaxf(m, g_e2[g_srt_eid[j]]);
        float s = 0.f;
        for (int j = beg; j < end; j++)
            s += __expf(g_e2[g_srt_eid[j]] - m);
        sm_m   = m;
        sm_inv = 1.0f / (s + 1e-16f);
    }
    __syncthreads();

    float m = sm_m, inv = sm_inv, acc = 0.f;
    for (int j = beg; j < end; j++) {
        int src = g_srt_src[j];
        int eid = g_srt_eid[j];
        float w = __expf(g_e2[eid] - m) * inv;
        acc = fmaf(g_h2[(size_t)src * OUT_CH + t], w, acc);
    }
    float v = acc + bias[t];
    out[(size_t)n * OUT_CH + t] = (v > 0.f) ? v : 0.f;
}

// ---------------------------------------------------------------------------
// Launch
// ---------------------------------------------------------------------------
extern "C" void kernel_launch(void* const* d_in, const int* in_sizes, int n_in,
                              void* d_out, int out_size) {
    const float* x      = (const float*)d_in[0];
    const int*   ei     = (const int*)d_in[1];     // int32 (JAX x64 disabled)
    const float* W1     = (const float*)d_in[2];
    const float* a_src1 = (const float*)d_in[3];
    const float* a_dst1 = (const float*)d_in[4];
    const float* b1     = (const float*)d_in[5];
    const float* W2     = (const float*)d_in[6];
    const float* a_src2 = (const float*)d_in[7];
    const float* a_dst2 = (const float*)d_in[8];
    const float* b2     = (const float*)d_in[9];
    float*       out    = (float*)d_out;

    // --- CSR build (by destination) ---
    zero_hist_kernel<<<(NN + 255) / 256, 256>>>();
    hist_kernel<<<(ETOT + 255) / 256, 256>>>(ei);
    scan_kernel<<<1, 1024>>>();
    scatter_kernel<<<(ETOT + 255) / 256, 256>>>(ei);

    // --- Layer 1 ---
    {
        dim3 grid((HID + BN - 1) / BN, (NN + BM - 1) / BM);
        gemm1_kernel<<<grid, 256>>>(x, W1);
    }
    attn1_kernel<<<NN, 128>>>(a_src1, a_dst1);
    edge1_kernel<<<(ETOT * H1 + 255) / 256, 256>>>(ei);
    agg1_kernel<<<NN, AGG1_THREADS>>>(b1);

    // --- Layer 2 ---
    {
        dim3 grid((OUT_CH + BN - 1) / BN, (NN + BM - 1) / BM);
        gemm2_kernel<<<grid, 256>>>(W2);
    }
    attn2_kernel<<<(NN * 32 + 255) / 256, 256>>>(a_src2, a_dst2);
    edge2_kernel<<<(ETOT + 255) / 256, 256>>>(ei);
    agg2_kernel<<<NN, OUT_CH>>>(b2, out);
}

// round 3
// speedup vs baseline: 1.1471x; 1.1471x over previous
#include <cuda_runtime.h>
#include <cuda_bf16.h>
#include <cstdint>

// ---------------------------------------------------------------------------
// Problem constants (EncoderGAT: 2-layer GAT, PyG-style, eval mode)
// ---------------------------------------------------------------------------
#define NN      20000     // nodes
#define EE      160000    // directed edges (before self-loops)
#define ETOT    (EE + NN) // edges + self-loops
#define IN_CH   128
#define H1      36        // heads layer 1
#define C1      36        // channels per head layer 1
#define HID     (H1 * C1) // 1296
#define OUT_CH  128

// ---------------------------------------------------------------------------
// Device scratch (static __device__ arrays; no dynamic allocation allowed)
// ---------------------------------------------------------------------------
__device__ __align__(16) float g_h1[(size_t)NN * HID];    // x @ W1          (103.7 MB)
__device__ __align__(16) float g_out1[(size_t)NN * HID];  // relu(agg1 + b1) (103.7 MB)
__device__ __align__(16) float g_h2[(size_t)NN * OUT_CH]; // out1 @ W2       (10.2 MB)
__device__ __align__(16) float g_as1[NN * H1];
__device__ __align__(16) float g_ad1[NN * H1];
__device__ __align__(16) float g_as2[NN];
__device__ __align__(16) float g_ad2[NN];
__device__ __align__(16) float g_e1[(size_t)ETOT * H1];   // edge logits layer 1
__device__ __align__(16) float g_e2[ETOT];                // layer 2
__device__ int   g_hist[NN];
__device__ int   g_rowptr[NN + 1];
__device__ int   g_cursor[NN];
__device__ int   g_srt_src[ETOT];               // CSR (by dst): src node per slot
__device__ int   g_srt_eid[ETOT];               // CSR: original edge id per slot

// ---------------------------------------------------------------------------
// Edge helpers: edges j < EE come from edge_index (int32), j >= EE self-loops
// ---------------------------------------------------------------------------
__device__ __forceinline__ int edge_src(const int* __restrict__ ei, int j) {
    return (j < EE) ? ei[j] : (j - EE);
}
__device__ __forceinline__ int edge_dst(const int* __restrict__ ei, int j) {
    return (j < EE) ? ei[EE + j] : (j - EE);
}

// ---------------------------------------------------------------------------
// CSR build: histogram -> scan -> scatter
// ---------------------------------------------------------------------------
__global__ void zero_hist_kernel() {
    int i = blockIdx.x * blockDim.x + threadIdx.x;
    if (i < NN) g_hist[i] = 0;
}

__global__ void hist_kernel(const int* __restrict__ ei) {
    int j = blockIdx.x * blockDim.x + threadIdx.x;
    if (j < ETOT) atomicAdd(&g_hist[edge_dst(ei, j)], 1);
}

// single-block inclusive scan over NN bins (chunked Hillis-Steele)
__global__ void scan_kernel() {
    __shared__ int sdata[1024];
    int t = threadIdx.x;
    if (t == 0) g_rowptr[0] = 0;
    int offset = 0;
    for (int base = 0; base < NN; base += 1024) {
        int v = (base + t < NN) ? g_hist[base + t] : 0;
        sdata[t] = v;
        __syncthreads();
        for (int d = 1; d < 1024; d <<= 1) {
            int add = (t >= d) ? sdata[t - d] : 0;
            __syncthreads();
            sdata[t] += add;
            __syncthreads();
        }
        int incl = sdata[t];
        if (base + t < NN) {
            g_rowptr[base + t + 1] = offset + incl;
            g_cursor[base + t]     = offset + incl - v;   // exclusive
        }
        offset += sdata[1023];
        __syncthreads();
    }
}

__global__ void scatter_kernel(const int* __restrict__ ei) {
    int j = blockIdx.x * blockDim.x + threadIdx.x;
    if (j >= ETOT) return;
    int d = edge_dst(ei, j);
    int pos = atomicAdd(&g_cursor[d], 1);
    g_srt_src[pos] = edge_src(ei, j);
    g_srt_eid[pos] = j;
}

// ---------------------------------------------------------------------------
// Tensor-core GEMM: C[M,N] = A[M,K] @ B[K,N], fp32 via 3xTF32 split.
//   mma.sync.aligned.m16n8k8.row.col.f32.tf32.tf32.f32
//   A = Ah + Al, B = Bh + Bl (tf32 splits); C ~= Ah*Bh + Ah*Bl + Al*Bh.
// Block tile 128x128, BK=16 (K % 16 == 0 holds: 128, 1296).
// 256 threads = 8 warps; warp tile 32(m) x 64(n) = 2 x 8 mma fragments.
// SMEM stride 136 words -> fragment loads are bank-conflict-free.
// ---------------------------------------------------------------------------
#define GBM 128
#define GBN 128
#define GBK 16
#define SMS 136

__device__ __forceinline__ uint32_t f2tf32(float x) {
    uint32_t r;
    asm("cvt.rna.tf32.f32 %0, %1;" : "=r"(r) : "f"(x));
    return r;
}

__device__ __forceinline__ void mma_tf32(float* c,
                                         uint32_t a0, uint32_t a1,
                                         uint32_t a2, uint32_t a3,
                                         uint32_t b0, uint32_t b1) {
    asm volatile(
        "mma.sync.aligned.m16n8k8.row.col.f32.tf32.tf32.f32 "
        "{%0,%1,%2,%3}, {%4,%5,%6,%7}, {%8,%9}, {%0,%1,%2,%3};\n"
        : "+f"(c[0]), "+f"(c[1]), "+f"(c[2]), "+f"(c[3])
        : "r"(a0), "r"(a1), "r"(a2), "r"(a3), "r"(b0), "r"(b1));
}

template <int Mv, int Nv, int Kv>
__device__ __forceinline__ void gemm_tc_body(const float* __restrict__ A,
                                             const float* __restrict__ B,
                                             float* __restrict__ C) {
    __shared__ uint32_t As_hi[GBK][SMS];
    __shared__ uint32_t As_lo[GBK][SMS];
    __shared__ uint32_t Bs_hi[GBK][SMS];
    __shared__ uint32_t Bs_lo[GBK][SMS];

    const int tid  = threadIdx.x;
    const int wid  = tid >> 5;
    const int lane = tid & 31;
    const int wm = (wid & 3) * 32;   // warp m offset within block tile
    const int wn = (wid >> 2) * 64;  // warp n offset
    const int g  = lane & 3;         // k group within fragment
    const int u  = lane >> 2;        // 0..7
    const int row0 = blockIdx.y * GBM;
    const int col0 = blockIdx.x * GBN;

    float acc[2][8][4];
    #pragma unroll
    for (int mt = 0; mt < 2; mt++)
        #pragma unroll
        for (int nt = 0; nt < 8; nt++)
            #pragma unroll
            for (int q = 0; q < 4; q++)
                acc[mt][nt][q] = 0.f;

    for (int kt = 0; kt < Kv / GBK; kt++) {
        const int kbase = kt * GBK;
        // ---- A tile: 128 x 16 floats = 512 float4, 2 per thread ----
        #pragma unroll
        for (int i = 0; i < 2; i++) {
            int q  = tid + i * 256;
            int m  = q >> 2;             // 0..127
            int k4 = (q & 3) * 4;        // 0,4,8,12
            float4 v = make_float4(0.f, 0.f, 0.f, 0.f);
            int gm = row0 + m;
            if (gm < Mv)
                v = *(const float4*)&A[(size_t)gm * Kv + kbase + k4];
            const float vv[4] = {v.x, v.y, v.z, v.w};
            #pragma unroll
            for (int j = 0; j < 4; j++) {
                uint32_t h = f2tf32(vv[j]);
                As_hi[k4 + j][m] = h;
                As_lo[k4 + j][m] = f2tf32(vv[j] - __uint_as_float(h));
            }
        }
        // ---- B tile: 16 x 128 floats = 512 float4, 2 per thread ----
        #pragma unroll
        for (int i = 0; i < 2; i++) {
            int q  = tid + i * 256;
            int k  = q >> 5;             // 0..15
            int n4 = (q & 31) * 4;       // 0..124
            int gn = col0 + n4;
            float4 v = make_float4(0.f, 0.f, 0.f, 0.f);
            const float* brow = &B[(size_t)(kbase + k) * Nv];
            if (gn + 3 < Nv) {
                v = *(const float4*)&brow[gn];
            } else {
                if (gn + 0 < Nv) v.x = brow[gn + 0];
                if (gn + 1 < Nv) v.y = brow[gn + 1];
                if (gn + 2 < Nv) v.z = brow[gn + 2];
                if (gn + 3 < Nv) v.w = brow[gn + 3];
            }
            const float vv[4] = {v.x, v.y, v.z, v.w};
            uint32_t hv[4], lv[4];
            #pragma unroll
            for (int j = 0; j < 4; j++) {
                hv[j] = f2tf32(vv[j]);
                lv[j] = f2tf32(vv[j] - __uint_as_float(hv[j]));
            }
            *(uint4*)&Bs_hi[k][n4] = make_uint4(hv[0], hv[1], hv[2], hv[3]);
            *(uint4*)&Bs_lo[k][n4] = make_uint4(lv[0], lv[1], lv[2], lv[3]);
        }
        __syncthreads();

        #pragma unroll
        for (int ks = 0; ks < 2; ks++) {
            const int kb = ks * 8;
            uint32_t ah[2][4], al[2][4];
            #pragma unroll
            for (int mt = 0; mt < 2; mt++) {
                int m0 = wm + mt * 16;
                ah[mt][0] = As_hi[kb + g][m0 + u];
                ah[mt][1] = As_hi[kb + g][m0 + u + 8];
                ah[mt][2] = As_hi[kb + g + 4][m0 + u];
                ah[mt][3] = As_hi[kb + g + 4][m0 + u + 8];
                al[mt][0] = As_lo[kb + g][m0 + u];
                al[mt][1] = As_lo[kb + g][m0 + u + 8];
                al[mt][2] = As_lo[kb + g + 4][m0 + u];
                al[mt][3] = As_lo[kb + g + 4][m0 + u + 8];
            }
            uint32_t bh[8][2], bl[8][2];
            #pragma unroll
            for (int nt = 0; nt < 8; nt++) {
                int n0 = wn + nt * 8;
                bh[nt][0] = Bs_hi[kb + g][n0 + u];
                bh[nt][1] = Bs_hi[kb + g + 4][n0 + u];
                bl[nt][0] = Bs_lo[kb + g][n0 + u];
                bl[nt][1] = Bs_lo[kb + g + 4][n0 + u];
            }
            #pragma unroll
            for (int mt = 0; mt < 2; mt++)
                #pragma unroll
                for (int nt = 0; nt < 8; nt++) {
                    mma_tf32(acc[mt][nt], ah[mt][0], ah[mt][1], ah[mt][2], ah[mt][3],
                             bh[nt][0], bh[nt][1]);
                    mma_tf32(acc[mt][nt], ah[mt][0], ah[mt][1], ah[mt][2], ah[mt][3],
                             bl[nt][0], bl[nt][1]);
                    mma_tf32(acc[mt][nt], al[mt][0], al[mt][1], al[mt][2], al[mt][3],
                             bh[nt][0], bh[nt][1]);
                }
        }
        __syncthreads();
    }

    // ---- epilogue: c0,c1 -> (row u, cols 2g,2g+1); c2,c3 -> row u+8 ----
    #pragma unroll
    for (int mt = 0; mt < 2; mt++) {
        int r0 = row0 + wm + mt * 16 + u;
        int r1 = r0 + 8;
        #pragma unroll
        for (int nt = 0; nt < 8; nt++) {
            int c = col0 + wn + nt * 8 + 2 * g;
            if (c < Nv) {  // c even, Nv even -> c+1 < Nv too
                if (r0 < Mv)
                    *(float2*)&C[(size_t)r0 * Nv + c] =
                        make_float2(acc[mt][nt][0], acc[mt][nt][1]);
                if (r1 < Mv)
                    *(float2*)&C[(size_t)r1 * Nv + c] =
                        make_float2(acc[mt][nt][2], acc[mt][nt][3]);
            }
        }
    }
}

__global__ void __launch_bounds__(256)
gemm1_kernel(const float* __restrict__ x, const float* __restrict__ W1) {
    gemm_tc_body<NN, HID, IN_CH>(x, W1, g_h1);
}

__global__ void __launch_bounds__(256)
gemm2_kernel(const float* __restrict__ W2) {
    gemm_tc_body<NN, OUT_CH, HID>(g_out1, W2, g_h2);
}

// ---------------------------------------------------------------------------
// Attention coefficients
// ---------------------------------------------------------------------------
__global__ void attn1_kernel(const float* __restrict__ a_src,
                             const float* __restrict__ a_dst) {
    int n = blockIdx.x;
    __shared__ float row[HID];
    const float* hrow = &g_h1[(size_t)n * HID];
    for (int c = threadIdx.x; c < HID; c += blockDim.x) row[c] = hrow[c];
    __syncthreads();
    int t = threadIdx.x;
    if (t < 2 * H1) {
        int h = (t < H1) ? t : (t - H1);
        const float* a = (t < H1) ? a_src : a_dst;
        float s = 0.f;
        #pragma unroll
        for (int c = 0; c < C1; c++) s = fmaf(row[h * C1 + c], a[h * C1 + c], s);
        if (t < H1) g_as1[n * H1 + h] = s;
        else        g_ad1[n * H1 + h] = s;
    }
}

__global__ void attn2_kernel(const float* __restrict__ a_src,
                             const float* __restrict__ a_dst) {
    int warp = (blockIdx.x * blockDim.x + threadIdx.x) >> 5;
    int lane = threadIdx.x & 31;
    if (warp >= NN) return;
    const float* hrow = &g_h2[(size_t)warp * OUT_CH];
    float4 v  = *(const float4*)&hrow[lane * 4];
    float4 as = *(const float4*)&a_src[lane * 4];
    float4 ad = *(const float4*)&a_dst[lane * 4];
    float ss = v.x * as.x + v.y * as.y + v.z * as.z + v.w * as.w;
    float sd = v.x * ad.x + v.y * ad.y + v.z * ad.z + v.w * ad.w;
    #pragma unroll
    for (int o = 16; o; o >>= 1) {
        ss += __shfl_xor_sync(0xFFFFFFFFu, ss, o);
        sd += __shfl_xor_sync(0xFFFFFFFFu, sd, o);
    }
    if (lane == 0) { g_as2[warp] = ss; g_ad2[warp] = sd; }
}

// ---------------------------------------------------------------------------
// Per-edge raw attention logits (leaky relu, slope 0.2)
// ---------------------------------------------------------------------------
__global__ void edge1_kernel(const int* __restrict__ ei) {
    int idx = blockIdx.x * blockDim.x + threadIdx.x;
    if (idx >= ETOT * H1) return;
    int e = idx / H1;
    int h = idx - e * H1;
    int s = edge_src(ei, e);
    int d = edge_dst(ei, e);
    float v = g_as1[s * H1 + h] + g_ad1[d * H1 + h];
    g_e1[idx] = (v > 0.f) ? v : 0.2f * v;
}

__global__ void edge2_kernel(const int* __restrict__ ei) {
    int e = blockIdx.x * blockDim.x + threadIdx.x;
    if (e >= ETOT) return;
    int s = edge_src(ei, e);
    int d = edge_dst(ei, e);
    float v = g_as2[s] + g_ad2[d];
    g_e2[e] = (v > 0.f) ? v : 0.2f * v;
}

// ---------------------------------------------------------------------------
// Layer-1 aggregation: per-dst softmax over in-edges + weighted sum of h1[src]
// ---------------------------------------------------------------------------
#define AGG1_THREADS 448
__global__ void __launch_bounds__(AGG1_THREADS)
agg1_kernel(const float* __restrict__ bias) {
    int n = blockIdx.x;
    int t = threadIdx.x;
    __shared__ float sm_m[H1];
    __shared__ float sm_inv[H1];

    int beg = g_rowptr[n];
    int end = g_rowptr[n + 1];

    if (t < H1) {
        float m = -1e30f;
        for (int j = beg; j < end; j++)
            m = fmaxf(m, g_e1[(size_t)g_srt_eid[j] * H1 + t]);
        float s = 0.f;
        for (int j = beg; j < end; j++)
            s += __expf(g_e1[(size_t)g_srt_eid[j] * H1 + t] - m);
        sm_m[t]   = m;
        sm_inv[t] = 1.0f / (s + 1e-16f);
    }
    __syncthreads();

    int c0 = t, c1 = t + AGG1_THREADS, c2 = t + 2 * AGG1_THREADS;
    int h0 = c0 / C1, h1h = c1 / C1, h2h = (c2 < HID) ? (c2 / C1) : 0;
    float m0 = sm_m[h0],  i0 = sm_inv[h0];
    float m1 = sm_m[h1h], i1 = sm_inv[h1h];
    float m2 = (c2 < HID) ? sm_m[h2h]   : 0.f;
    float i2 = (c2 < HID) ? sm_inv[h2h] : 0.f;

    float acc0 = 0.f, acc1 = 0.f, acc2 = 0.f;
    for (int j = beg; j < end; j++) {
        int src = g_srt_src[j];
        int eid = g_srt_eid[j];
        const float* hrow = &g_h1[(size_t)src * HID];
        const float* erow = &g_e1[(size_t)eid * H1];
        float w0 = __expf(erow[h0]  - m0) * i0;
        float w1 = __expf(erow[h1h] - m1) * i1;
        acc0 = fmaf(hrow[c0], w0, acc0);
        acc1 = fmaf(hrow[c1], w1, acc1);
        if (c2 < HID) {
            float w2 = __expf(erow[h2h] - m2) * i2;
            acc2 = fmaf(hrow[c2], w2, acc2);
        }
    }

    float* orow = &g_out1[(size_t)n * HID];
    float v0 = acc0 + bias[c0];
    orow[c0] = (v0 > 0.f) ? v0 : 0.f;
    float v1 = acc1 + bias[c1];
    orow[c1] = (v1 > 0.f) ? v1 : 0.f;
    if (c2 < HID) {
        float v2 = acc2 + bias[c2];
        orow[c2] = (v2 > 0.f) ? v2 : 0.f;
    }
}

// ---------------------------------------------------------------------------
// Layer-2 aggregation (1 head, 128 channels) -> final output with bias + relu
// ---------------------------------------------------------------------------
__global__ void __launch_bounds__(OUT_CH)
agg2_kernel(const float* __restrict__ bias, float* __restrict__ out) {
    int n = blockIdx.x;
    int t = threadIdx.x;
    __shared__ float sm_m, sm_inv;

    int beg = g_rowptr[n];
    int end = g_rowptr[n + 1];

    if (t == 0) {
        float m = -1e30f;
        for (int j = beg; j < end; j++)
            m = fmaxf(m, g_e2[g_srt_eid[j]]);
        float s = 0.f;
        for (int j = beg; j < end; j++)
            s += __expf(g_e2[g_srt_eid[j]] - m);
        sm_m   = m;
        sm_inv = 1.0f / (s + 1e-16f);
    }
    __syncthreads();

    float m = sm_m, inv = sm_inv, acc = 0.f;
    for (int j = beg; j < end; j++) {
        int src = g_srt_src[j];
        int eid = g_srt_eid[j];
        float w = __expf(g_e2[eid] - m) * inv;
        acc = fmaf(g_h2[(size_t)src * OUT_CH + t], w, acc);
    }
    float v = acc + bias[t];
    out[(size_t)n * OUT_CH + t] = (v > 0.f) ? v : 0.f;
}

// ---------------------------------------------------------------------------
// Launch
// ---------------------------------------------------------------------------
extern "C" void kernel_launch(void* const* d_in, const int* in_sizes, int n_in,
                              void* d_out, int out_size) {
    const float* x      = (const float*)d_in[0];
    const int*   ei     = (const int*)d_in[1];     // int32 (JAX x64 disabled)
    const float* W1     = (const float*)d_in[2];
    const float* a_src1 = (const float*)d_in[3];
    const float* a_dst1 = (const float*)d_in[4];
    const float* b1     = (const float*)d_in[5];
    const float* W2     = (const float*)d_in[6];
    const float* a_src2 = (const float*)d_in[7];
    const float* a_dst2 = (const float*)d_in[8];
    const float* b2     = (const float*)d_in[9];
    float*       out    = (float*)d_out;

    // --- CSR build (by destination) ---
    zero_hist_kernel<<<(NN + 255) / 256, 256>>>();
    hist_kernel<<<(ETOT + 255) / 256, 256>>>(ei);
    scan_kernel<<<1, 1024>>>();
    scatter_kernel<<<(ETOT + 255) / 256, 256>>>(ei);

    // --- Layer 1 ---
    {
        dim3 grid((HID + GBN - 1) / GBN, (NN + GBM - 1) / GBM);
        gemm1_kernel<<<grid, 256>>>(x, W1);
    }
    attn1_kernel<<<NN, 128>>>(a_src1, a_dst1);
    edge1_kernel<<<(ETOT * H1 + 255) / 256, 256>>>(ei);
    agg1_kernel<<<NN, AGG1_THREADS>>>(b1);

    // --- Layer 2 ---
    {
        dim3 grid((OUT_CH + GBN - 1) / GBN, (NN + GBM - 1) / GBM);
        gemm2_kernel<<<grid, 256>>>(W2);
    }
    attn2_kernel<<<(NN * 32 + 255) / 256, 256>>>(a_src2, a_dst2);
    edge2_kernel<<<(ETOT + 255) / 256, 256>>>(ei);
    agg2_kernel<<<NN, OUT_CH>>>(b2, out);
}

// round 5
// speedup vs baseline: 1.3642x; 1.1892x over previous
#include <cuda_runtime.h>
#include <cuda_bf16.h>
#include <cstdint>

// ---------------------------------------------------------------------------
// Problem constants
// ---------------------------------------------------------------------------
#define NN      20000
#define EE      160000
#define ETOT    (EE + NN)
#define IN_CH   128
#define H1      36
#define C1      36
#define HID     (H1 * C1)   // 1296
#define OUT_CH  128

// ---------------------------------------------------------------------------
// Device scratch
// ---------------------------------------------------------------------------
__device__ __align__(16) float g_h1[(size_t)NN * HID];     // x @ W1 (fp32)
__device__ __align__(16) float g_o1h[(size_t)NN * HID];    // relu(agg1) tf32-hi
__device__ __align__(16) float g_o1l[(size_t)NN * HID];    // relu(agg1) tf32-lo
__device__ __align__(16) float g_h2[(size_t)NN * OUT_CH];  // out1 @ W2 (fp32)
__device__ __align__(16) float g_xh[(size_t)NN * IN_CH];   // x split
__device__ __align__(16) float g_xl[(size_t)NN * IN_CH];
__device__ __align__(16) float g_w1h[IN_CH * HID];
__device__ __align__(16) float g_w1l[IN_CH * HID];
__device__ __align__(16) float g_w2h[HID * OUT_CH];
__device__ __align__(16) float g_w2l[HID * OUT_CH];
__device__ __align__(16) float g_as1[NN * H1];
__device__ __align__(16) float g_ad1[NN * H1];
__device__ __align__(16) float g_as2[NN];
__device__ __align__(16) float g_ad2[NN];
__device__ int g_hist[NN];
__device__ int g_rowptr[NN + 1];
__device__ int g_cursor[NN];
__device__ int g_srt_src[ETOT];

// ---------------------------------------------------------------------------
// tf32 helpers
// ---------------------------------------------------------------------------
__device__ __forceinline__ uint32_t f2tf32(float x) {
    uint32_t r;
    asm("cvt.rna.tf32.f32 %0, %1;" : "=r"(r) : "f"(x));
    return r;
}
__device__ __forceinline__ void split_tf32(float v, float& hi, float& lo) {
    uint32_t h = f2tf32(v);
    hi = __uint_as_float(h);
    lo = __uint_as_float(f2tf32(v - __uint_as_float(h)));
}

__device__ __forceinline__ void mma_tf32(float* c,
                                         uint32_t a0, uint32_t a1,
                                         uint32_t a2, uint32_t a3,
                                         uint32_t b0, uint32_t b1) {
    asm volatile(
        "mma.sync.aligned.m16n8k8.row.col.f32.tf32.tf32.f32 "
        "{%0,%1,%2,%3}, {%4,%5,%6,%7}, {%8,%9}, {%0,%1,%2,%3};\n"
        : "+f"(c[0]), "+f"(c[1]), "+f"(c[2]), "+f"(c[3])
        : "r"(a0), "r"(a1), "r"(a2), "r"(a3), "r"(b0), "r"(b1));
}

__device__ __forceinline__ void cp_async16(uint32_t dst, const float* src, bool pred) {
    int sz = pred ? 16 : 0;
    asm volatile("cp.async.ca.shared.global [%0], [%1], 16, %2;\n"
                 :: "r"(dst), "l"(src), "r"(sz));
}
__device__ __forceinline__ void cp_commit() {
    asm volatile("cp.async.commit_group;\n");
}
template <int N>
__device__ __forceinline__ void cp_wait() {
    asm volatile("cp.async.wait_group %0;\n" :: "n"(N));
}

// ---------------------------------------------------------------------------
// tf32 split kernels. NOTE: __device__ globals referenced directly — never
// passed as host-side launch arguments (host sees only shadow symbols).
// ---------------------------------------------------------------------------
__device__ __forceinline__ void split_loop(const float* __restrict__ src,
                                           float* __restrict__ hi,
                                           float* __restrict__ lo, int n) {
    for (int i = blockIdx.x * blockDim.x + threadIdx.x; i < n;
         i += gridDim.x * blockDim.x) {
        float h, l;
        split_tf32(src[i], h, l);
        hi[i] = h; lo[i] = l;
    }
}
__global__ void split_x_kernel(const float* __restrict__ src) {
    split_loop(src, g_xh, g_xl, NN * IN_CH);
}
__global__ void split_w1_kernel(const float* __restrict__ src) {
    split_loop(src, g_w1h, g_w1l, IN_CH * HID);
}
__global__ void split_w2_kernel(const float* __restrict__ src) {
    split_loop(src, g_w2h, g_w2l, HID * OUT_CH);
}

// ---------------------------------------------------------------------------
// Edge helpers (edge_index is int32; j >= EE are self-loops)
// ---------------------------------------------------------------------------
__device__ __forceinline__ int edge_src(const int* __restrict__ ei, int j) {
    return (j < EE) ? ei[j] : (j - EE);
}
__device__ __forceinline__ int edge_dst(const int* __restrict__ ei, int j) {
    return (j < EE) ? ei[EE + j] : (j - EE);
}

// ---------------------------------------------------------------------------
// CSR build
// ---------------------------------------------------------------------------
__global__ void zero_hist_kernel() {
    int i = blockIdx.x * blockDim.x + threadIdx.x;
    if (i < NN) g_hist[i] = 0;
}
__global__ void hist_kernel(const int* __restrict__ ei) {
    int j = blockIdx.x * blockDim.x + threadIdx.x;
    if (j < ETOT) atomicAdd(&g_hist[edge_dst(ei, j)], 1);
}
__global__ void scan_kernel() {
    __shared__ int sdata[1024];
    int t = threadIdx.x;
    if (t == 0) g_rowptr[0] = 0;
    int offset = 0;
    for (int base = 0; base < NN; base += 1024) {
        int v = (base + t < NN) ? g_hist[base + t] : 0;
        sdata[t] = v;
        __syncthreads();
        for (int d = 1; d < 1024; d <<= 1) {
            int add = (t >= d) ? sdata[t - d] : 0;
            __syncthreads();
            sdata[t] += add;
            __syncthreads();
        }
        int incl = sdata[t];
        if (base + t < NN) {
            g_rowptr[base + t + 1] = offset + incl;
            g_cursor[base + t]     = offset + incl - v;
        }
        offset += sdata[1023];
        __syncthreads();
    }
}
__global__ void scatter_kernel(const int* __restrict__ ei) {
    int j = blockIdx.x * blockDim.x + threadIdx.x;
    if (j >= ETOT) return;
    int d = edge_dst(ei, j);
    int pos = atomicAdd(&g_cursor[d], 1);
    g_srt_src[pos] = edge_src(ei, j);
}

// ---------------------------------------------------------------------------
// Pre-split tf32 GEMM, double-buffered cp.async pipeline.
// C[M,N] = (Ah+Al)(Bh+Bl) ~= Ah*Bh + Ah*Bl + Al*Bh  (3x tf32 MMA)
// BK = 8, block = 256 threads (8 warps).
// GBMv=128: warp tile 32x64 (MT=2, NT=8); GBMv=64: warp tile 32x32 (NT=4).
// ---------------------------------------------------------------------------
template <int Mv, int Nv, int Kv, int GBMv>
__device__ __forceinline__ void gemm_ps_body(const float* __restrict__ Ah,
                                             const float* __restrict__ Al,
                                             const float* __restrict__ Bh,
                                             const float* __restrict__ Bl,
                                             float* __restrict__ C) {
    constexpr int NT = (GBMv == 128) ? 8 : 4;
    constexpr int KT = Kv / 8;

    __shared__ __align__(16) float AsH[2][GBMv][12];
    __shared__ __align__(16) float AsL[2][GBMv][12];
    __shared__ __align__(16) float BsH[2][8][136];
    __shared__ __align__(16) float BsL[2][8][136];

    const int tid  = threadIdx.x;
    const int wid  = tid >> 5;
    const int lane = tid & 31;
    const int WM = (GBMv == 128) ? ((wid & 3) * 32) : ((wid & 1) * 32);
    const int WN = (GBMv == 128) ? ((wid >> 2) * 64) : ((wid >> 1) * 32);
    const int g = lane & 3;
    const int u = lane >> 2;
    const int row0 = blockIdx.y * GBMv;
    const int col0 = blockIdx.x * 128;

    const int am  = (GBMv == 128) ? (tid >> 1) : ((tid & 127) >> 1);
    const int ak4 = (tid & 1) * 4;
    const bool a_active = (GBMv == 128) || (tid < 128);
    const int bk  = tid >> 5;
    const int bn4 = (tid & 31) * 4;

    float acc[2][NT][4];
    #pragma unroll
    for (int mt = 0; mt < 2; mt++)
        #pragma unroll
        for (int nt = 0; nt < NT; nt++)
            #pragma unroll
            for (int q = 0; q < 4; q++) acc[mt][nt][q] = 0.f;

    auto prefetch = [&](int kt, int buf) {
        const int kbase = kt * 8;
        if (a_active) {
            int gm = row0 + am;
            bool p = (gm < Mv);
            int gmc = p ? gm : 0;
            uint32_t dh = (uint32_t)__cvta_generic_to_shared(&AsH[buf][am][ak4]);
            uint32_t dl = (uint32_t)__cvta_generic_to_shared(&AsL[buf][am][ak4]);
            cp_async16(dh, &Ah[(size_t)gmc * Kv + kbase + ak4], p);
            cp_async16(dl, &Al[(size_t)gmc * Kv + kbase + ak4], p);
        }
        {
            int gn = col0 + bn4;
            bool p = (gn < Nv);
            int gnc = p ? gn : 0;
            uint32_t dh = (uint32_t)__cvta_generic_to_shared(&BsH[buf][bk][bn4]);
            uint32_t dl = (uint32_t)__cvta_generic_to_shared(&BsL[buf][bk][bn4]);
            cp_async16(dh, &Bh[(size_t)(kbase + bk) * Nv + gnc], p);
            cp_async16(dl, &Bl[(size_t)(kbase + bk) * Nv + gnc], p);
        }
        cp_commit();
    };

    prefetch(0, 0);

    for (int kt = 0; kt < KT; kt++) {
        const int buf = kt & 1;
        if (kt + 1 < KT) {
            prefetch(kt + 1, buf ^ 1);
            cp_wait<1>();
        } else {
            cp_wait<0>();
        }
        __syncthreads();

        uint32_t ah[2][4], al[2][4], bh[NT][2], bl[NT][2];
        #pragma unroll
        for (int mt = 0; mt < 2; mt++) {
            int m0 = WM + mt * 16;
            ah[mt][0] = __float_as_uint(AsH[buf][m0 + u][g]);
            ah[mt][1] = __float_as_uint(AsH[buf][m0 + u + 8][g]);
            ah[mt][2] = __float_as_uint(AsH[buf][m0 + u][g + 4]);
            ah[mt][3] = __float_as_uint(AsH[buf][m0 + u + 8][g + 4]);
            al[mt][0] = __float_as_uint(AsL[buf][m0 + u][g]);
            al[mt][1] = __float_as_uint(AsL[buf][m0 + u + 8][g]);
            al[mt][2] = __float_as_uint(AsL[buf][m0 + u][g + 4]);
            al[mt][3] = __float_as_uint(AsL[buf][m0 + u + 8][g + 4]);
        }
        #pragma unroll
        for (int nt = 0; nt < NT; nt++) {
            int n0 = WN + nt * 8;
            bh[nt][0] = __float_as_uint(BsH[buf][g][n0 + u]);
            bh[nt][1] = __float_as_uint(BsH[buf][g + 4][n0 + u]);
            bl[nt][0] = __float_as_uint(BsL[buf][g][n0 + u]);
            bl[nt][1] = __float_as_uint(BsL[buf][g + 4][n0 + u]);
        }
        #pragma unroll
        for (int mt = 0; mt < 2; mt++)
            #pragma unroll
            for (int nt = 0; nt < NT; nt++) {
                mma_tf32(acc[mt][nt], ah[mt][0], ah[mt][1], ah[mt][2], ah[mt][3],
                         bh[nt][0], bh[nt][1]);
                mma_tf32(acc[mt][nt], ah[mt][0], ah[mt][1], ah[mt][2], ah[mt][3],
                         bl[nt][0], bl[nt][1]);
                mma_tf32(acc[mt][nt], al[mt][0], al[mt][1], al[mt][2], al[mt][3],
                         bh[nt][0], bh[nt][1]);
            }
        __syncthreads();
    }

    #pragma unroll
    for (int mt = 0; mt < 2; mt++) {
        int r0 = row0 + WM + mt * 16 + u;
        int r1 = r0 + 8;
        #pragma unroll
        for (int nt = 0; nt < NT; nt++) {
            int c = col0 + WN + nt * 8 + 2 * g;
            if (c < Nv) {
                if (r0 < Mv)
                    *(float2*)&C[(size_t)r0 * Nv + c] =
                        make_float2(acc[mt][nt][0], acc[mt][nt][1]);
                if (r1 < Mv)
                    *(float2*)&C[(size_t)r1 * Nv + c] =
                        make_float2(acc[mt][nt][2], acc[mt][nt][3]);
            }
        }
    }
}

__global__ void __launch_bounds__(256)
gemm1_kernel() {
    gemm_ps_body<NN, HID, IN_CH, 128>(g_xh, g_xl, g_w1h, g_w1l, g_h1);
}
__global__ void __launch_bounds__(256, 2)
gemm2_kernel() {
    gemm_ps_body<NN, OUT_CH, HID, 64>(g_o1h, g_o1l, g_w2h, g_w2l, g_h2);
}

// ---------------------------------------------------------------------------
// Attention coefficients
// ---------------------------------------------------------------------------
__global__ void attn1_kernel(const float* __restrict__ a_src,
                             const float* __restrict__ a_dst) {
    int n = blockIdx.x;
    __shared__ float row[HID];
    const float* hrow = &g_h1[(size_t)n * HID];
    for (int c = threadIdx.x; c < HID; c += blockDim.x) row[c] = hrow[c];
    __syncthreads();
    int t = threadIdx.x;
    if (t < 2 * H1) {
        int h = (t < H1) ? t : (t - H1);
        const float* a = (t < H1) ? a_src : a_dst;
        float s = 0.f;
        #pragma unroll
        for (int c = 0; c < C1; c++) s = fmaf(row[h * C1 + c], a[h * C1 + c], s);
        if (t < H1) g_as1[n * H1 + h] = s;
        else        g_ad1[n * H1 + h] = s;
    }
}

__global__ void attn2_kernel(const float* __restrict__ a_src,
                             const float* __restrict__ a_dst) {
    int warp = (blockIdx.x * blockDim.x + threadIdx.x) >> 5;
    int lane = threadIdx.x & 31;
    if (warp >= NN) return;
    const float* hrow = &g_h2[(size_t)warp * OUT_CH];
    float4 v  = *(const float4*)&hrow[lane * 4];
    float4 as = *(const float4*)&a_src[lane * 4];
    float4 ad = *(const float4*)&a_dst[lane * 4];
    float ss = v.x * as.x + v.y * as.y + v.z * as.z + v.w * as.w;
    float sd = v.x * ad.x + v.y * ad.y + v.z * ad.z + v.w * ad.w;
    #pragma unroll
    for (int o = 16; o; o >>= 1) {
        ss += __shfl_xor_sync(0xFFFFFFFFu, ss, o);
        sd += __shfl_xor_sync(0xFFFFFFFFu, sd, o);
    }
    if (lane == 0) { g_as2[warp] = ss; g_ad2[warp] = sd; }
}

// ---------------------------------------------------------------------------
// Layer-1 aggregation, fused softmax. 432 threads; thread t owns channels
// t, t+432, t+864 (heads h0, h0+12, h0+24 with h0 = t/36).
// Per-edge weights computed ONCE per (edge, head) into smem chunks.
// Epilogue writes tf32 hi/lo split of relu(out+bias) for gemm2.
// ---------------------------------------------------------------------------
#define AGG1_T 432
#define CE1    12
__global__ void __launch_bounds__(AGG1_T)
agg1_kernel(const float* __restrict__ bias) {
    int n = blockIdx.x;
    int t = threadIdx.x;
    __shared__ float sm_m[H1], sm_inv[H1], sm_ad[H1];
    __shared__ float w[CE1][H1];
    __shared__ int   ssrc[CE1];

    int beg = g_rowptr[n];
    int end = g_rowptr[n + 1];

    // phase 1: per-head max & sum (36 threads, serial over in-edges)
    if (t < H1) {
        float adn = g_ad1[n * H1 + t];
        sm_ad[t] = adn;
        float m = -1e30f;
        for (int j = beg; j < end; j++) {
            int s = g_srt_src[j];
            float v = g_as1[s * H1 + t] + adn;
            v = (v > 0.f) ? v : 0.2f * v;
            m = fmaxf(m, v);
        }
        float sum = 0.f;
        for (int j = beg; j < end; j++) {
            int s = g_srt_src[j];
            float v = g_as1[s * H1 + t] + adn;
            v = (v > 0.f) ? v : 0.2f * v;
            sum += __expf(v - m);
        }
        sm_m[t]   = m;
        sm_inv[t] = 1.0f / (sum + 1e-16f);
    }
    __syncthreads();

    const int c0 = t, c1 = t + AGG1_T, c2 = t + 2 * AGG1_T;
    const int h0 = t / H1;            // 0..11
    const int h1h = h0 + 12, h2h = h0 + 24;
    float acc0 = 0.f, acc1 = 0.f, acc2 = 0.f;

    for (int j0 = beg; j0 < end; j0 += CE1) {
        int cnt = end - j0; if (cnt > CE1) cnt = CE1;
        if (t < cnt) ssrc[t] = g_srt_src[j0 + t];
        __syncthreads();
        if (t < cnt * H1) {
            int e = t / H1, h = t - e * H1;
            float v = g_as1[ssrc[e] * H1 + h] + sm_ad[h];
            v = (v > 0.f) ? v : 0.2f * v;
            w[e][h] = __expf(v - sm_m[h]) * sm_inv[h];
        }
        __syncthreads();
        for (int e = 0; e < cnt; e++) {
            const float* hrow = &g_h1[(size_t)ssrc[e] * HID];
            acc0 = fmaf(hrow[c0], w[e][h0],  acc0);
            acc1 = fmaf(hrow[c1], w[e][h1h], acc1);
            acc2 = fmaf(hrow[c2], w[e][h2h], acc2);
        }
        __syncthreads();
    }

    float* oh = &g_o1h[(size_t)n * HID];
    float* ol = &g_o1l[(size_t)n * HID];
    float v0 = acc0 + bias[c0]; v0 = (v0 > 0.f) ? v0 : 0.f;
    float v1 = acc1 + bias[c1]; v1 = (v1 > 0.f) ? v1 : 0.f;
    float v2 = acc2 + bias[c2]; v2 = (v2 > 0.f) ? v2 : 0.f;
    float h, l;
    split_tf32(v0, h, l); oh[c0] = h; ol[c0] = l;
    split_tf32(v1, h, l); oh[c1] = h; ol[c1] = l;
    split_tf32(v2, h, l); oh[c2] = h; ol[c2] = l;
}

// ---------------------------------------------------------------------------
// Layer-2 aggregation (1 head, 128 ch), fused softmax, chunked weights.
// ---------------------------------------------------------------------------
#define CE2 32
__global__ void __launch_bounds__(128)
agg2_kernel(const float* __restrict__ bias, float* __restrict__ out) {
    int n = blockIdx.x;
    int t = threadIdx.x;
    __shared__ float red[128];
    __shared__ float w2[CE2];
    __shared__ int   ssrc2[CE2];

    int beg = g_rowptr[n];
    int end = g_rowptr[n + 1];
    float adn = g_ad2[n];

    // block max
    float lm = -1e30f;
    for (int j = beg + t; j < end; j += 128) {
        float v = g_as2[g_srt_src[j]] + adn;
        v = (v > 0.f) ? v : 0.2f * v;
        lm = fmaxf(lm, v);
    }
    red[t] = lm;
    __syncthreads();
    for (int o = 64; o; o >>= 1) {
        if (t < o) red[t] = fmaxf(red[t], red[t + o]);
        __syncthreads();
    }
    float m = red[0];
    __syncthreads();

    // block sum of exp
    float ls = 0.f;
    for (int j = beg + t; j < end; j += 128) {
        float v = g_as2[g_srt_src[j]] + adn;
        v = (v > 0.f) ? v : 0.2f * v;
        ls += __expf(v - m);
    }
    red[t] = ls;
    __syncthreads();
    for (int o = 64; o; o >>= 1) {
        if (t < o) red[t] += red[t + o];
        __syncthreads();
    }
    float inv = 1.0f / (red[0] + 1e-16f);
    __syncthreads();

    float acc = 0.f;
    for (int j0 = beg; j0 < end; j0 += CE2) {
        int cnt = end - j0; if (cnt > CE2) cnt = CE2;
        if (t < cnt) {
            int s = g_srt_src[j0 + t];
            ssrc2[t] = s;
            float v = g_as2[s] + adn;
            v = (v > 0.f) ? v : 0.2f * v;
            w2[t] = __expf(v - m) * inv;
        }
        __syncthreads();
        for (int e = 0; e < cnt; e++)
            acc = fmaf(g_h2[(size_t)ssrc2[e] * OUT_CH + t], w2[e], acc);
        __syncthreads();
    }

    float v = acc + bias[t];
    out[(size_t)n * OUT_CH + t] = (v > 0.f) ? v : 0.f;
}

// ---------------------------------------------------------------------------
// Launch
// ---------------------------------------------------------------------------
extern "C" void kernel_launch(void* const* d_in, const int* in_sizes, int n_in,
                              void* d_out, int out_size) {
    const float* x      = (const float*)d_in[0];
    const int*   ei     = (const int*)d_in[1];
    const float* W1     = (const float*)d_in[2];
    const float* a_src1 = (const float*)d_in[3];
    const float* a_dst1 = (const float*)d_in[4];
    const float* b1     = (const float*)d_in[5];
    const float* W2     = (const float*)d_in[6];
    const float* a_src2 = (const float*)d_in[7];
    const float* a_dst2 = (const float*)d_in[8];
    const float* b2     = (const float*)d_in[9];
    float*       out    = (float*)d_out;

    // tf32 splits of static operands (globals referenced in-device)
    split_x_kernel<<<512, 256>>>(x);
    split_w1_kernel<<<128, 256>>>(W1);
    split_w2_kernel<<<128, 256>>>(W2);

    // CSR build (by destination)
    zero_hist_kernel<<<(NN + 255) / 256, 256>>>();
    hist_kernel<<<(ETOT + 255) / 256, 256>>>(ei);
    scan_kernel<<<1, 1024>>>();
    scatter_kernel<<<(ETOT + 255) / 256, 256>>>(ei);

    // Layer 1
    {
        dim3 grid((HID + 127) / 128, (NN + 127) / 128);   // 11 x 157
        gemm1_kernel<<<grid, 256>>>();
    }
    attn1_kernel<<<NN, 128>>>(a_src1, a_dst1);
    agg1_kernel<<<NN, AGG1_T>>>(b1);

    // Layer 2
    {
        dim3 grid(1, (NN + 63) / 64);                     // 1 x 313
        gemm2_kernel<<<grid, 256>>>();
    }
    attn2_kernel<<<(NN * 32 + 255) / 256, 256>>>(a_src2, a_dst2);
    agg2_kernel<<<NN, 128>>>(b2, out);
}

// round 6
// speedup vs baseline: 1.4619x; 1.0716x over previous
#include <cuda_runtime.h>
#include <cuda_bf16.h>
#include <cstdint>

// ---------------------------------------------------------------------------
// Problem constants
// ---------------------------------------------------------------------------
#define NN      20000
#define EE      160000
#define ETOT    (EE + NN)
#define IN_CH   128
#define H1      36
#define C1      36
#define HID     (H1 * C1)   // 1296
#define OUT_CH  128

// ---------------------------------------------------------------------------
// Device scratch
// ---------------------------------------------------------------------------
__device__ __align__(16) float g_h1[(size_t)NN * HID];     // x @ W1 (fp32)
__device__ __align__(16) float g_o1h[(size_t)NN * HID];    // relu(agg1) tf32-hi
__device__ __align__(16) float g_o1l[(size_t)NN * HID];    // relu(agg1) tf32-lo
__device__ __align__(16) float g_h2[(size_t)NN * OUT_CH];  // out1 @ W2 (fp32)
__device__ __align__(16) float g_xh[(size_t)NN * IN_CH];
__device__ __align__(16) float g_xl[(size_t)NN * IN_CH];
__device__ __align__(16) float g_w1h[IN_CH * HID];
__device__ __align__(16) float g_w1l[IN_CH * HID];
__device__ __align__(16) float g_w2h[HID * OUT_CH];
__device__ __align__(16) float g_w2l[HID * OUT_CH];
__device__ __align__(16) float g_as1[NN * H1];
__device__ __align__(16) float g_ad1[NN * H1];
__device__ __align__(16) float g_m1[NN * H1];     // layer-1 softmax max
__device__ __align__(16) float g_i1[NN * H1];     // layer-1 softmax 1/sum
__device__ __align__(16) float g_as2[NN];
__device__ __align__(16) float g_ad2[NN];
__device__ int g_hist[NN];
__device__ int g_rowptr[NN + 1];
__device__ int g_cursor[NN];
__device__ int g_srt_src[ETOT];

// ---------------------------------------------------------------------------
// tf32 helpers
// ---------------------------------------------------------------------------
__device__ __forceinline__ uint32_t f2tf32(float x) {
    uint32_t r;
    asm("cvt.rna.tf32.f32 %0, %1;" : "=r"(r) : "f"(x));
    return r;
}
__device__ __forceinline__ void split_tf32(float v, float& hi, float& lo) {
    uint32_t h = f2tf32(v);
    hi = __uint_as_float(h);
    lo = __uint_as_float(f2tf32(v - __uint_as_float(h)));
}

__device__ __forceinline__ void mma_tf32(float* c,
                                         uint32_t a0, uint32_t a1,
                                         uint32_t a2, uint32_t a3,
                                         uint32_t b0, uint32_t b1) {
    asm volatile(
        "mma.sync.aligned.m16n8k8.row.col.f32.tf32.tf32.f32 "
        "{%0,%1,%2,%3}, {%4,%5,%6,%7}, {%8,%9}, {%0,%1,%2,%3};\n"
        : "+f"(c[0]), "+f"(c[1]), "+f"(c[2]), "+f"(c[3])
        : "r"(a0), "r"(a1), "r"(a2), "r"(a3), "r"(b0), "r"(b1));
}

__device__ __forceinline__ void cp_async16(uint32_t dst, const float* src, bool pred) {
    int sz = pred ? 16 : 0;
    asm volatile("cp.async.ca.shared.global [%0], [%1], 16, %2;\n"
                 :: "r"(dst), "l"(src), "r"(sz));
}
__device__ __forceinline__ void cp_commit() {
    asm volatile("cp.async.commit_group;\n");
}
template <int N>
__device__ __forceinline__ void cp_wait() {
    asm volatile("cp.async.wait_group %0;\n" :: "n"(N));
}

// ---------------------------------------------------------------------------
// prep: tf32 splits of x/W1/W2 + zero hist (one kernel, launch #1)
// __device__ globals referenced in device code only.
// ---------------------------------------------------------------------------
__global__ void prep_kernel(const float* __restrict__ x,
                            const float* __restrict__ W1,
                            const float* __restrict__ W2) {
    int stride = gridDim.x * blockDim.x;
    int tid0 = blockIdx.x * blockDim.x + threadIdx.x;
    for (int i = tid0; i < NN * IN_CH; i += stride) {
        float h, l; split_tf32(x[i], h, l);
        g_xh[i] = h; g_xl[i] = l;
    }
    for (int i = tid0; i < IN_CH * HID; i += stride) {
        float h, l; split_tf32(W1[i], h, l);
        g_w1h[i] = h; g_w1l[i] = l;
    }
    for (int i = tid0; i < HID * OUT_CH; i += stride) {
        float h, l; split_tf32(W2[i], h, l);
        g_w2h[i] = h; g_w2l[i] = l;
    }
    for (int i = tid0; i < NN; i += stride) g_hist[i] = 0;
}

// ---------------------------------------------------------------------------
// Edge helpers (edge_index is int32; j >= EE are self-loops)
// ---------------------------------------------------------------------------
__device__ __forceinline__ int edge_src(const int* __restrict__ ei, int j) {
    return (j < EE) ? ei[j] : (j - EE);
}
__device__ __forceinline__ int edge_dst(const int* __restrict__ ei, int j) {
    return (j < EE) ? ei[EE + j] : (j - EE);
}

// ---------------------------------------------------------------------------
// CSR build
// ---------------------------------------------------------------------------
__global__ void hist_kernel(const int* __restrict__ ei) {
    int j = blockIdx.x * blockDim.x + threadIdx.x;
    if (j < ETOT) atomicAdd(&g_hist[edge_dst(ei, j)], 1);
}
__global__ void scan_kernel() {
    __shared__ int sdata[1024];
    int t = threadIdx.x;
    if (t == 0) g_rowptr[0] = 0;
    int offset = 0;
    for (int base = 0; base < NN; base += 1024) {
        int v = (base + t < NN) ? g_hist[base + t] : 0;
        sdata[t] = v;
        __syncthreads();
        for (int d = 1; d < 1024; d <<= 1) {
            int add = (t >= d) ? sdata[t - d] : 0;
            __syncthreads();
            sdata[t] += add;
            __syncthreads();
        }
        int incl = sdata[t];
        if (base + t < NN) {
            g_rowptr[base + t + 1] = offset + incl;
            g_cursor[base + t]     = offset + incl - v;
        }
        offset += sdata[1023];
        __syncthreads();
    }
}
__global__ void scatter_kernel(const int* __restrict__ ei) {
    int j = blockIdx.x * blockDim.x + threadIdx.x;
    if (j >= ETOT) return;
    int d = edge_dst(ei, j);
    int pos = atomicAdd(&g_cursor[d], 1);
    g_srt_src[pos] = edge_src(ei, j);
}

// ---------------------------------------------------------------------------
// Pre-split tf32 GEMM, double-buffered cp.async pipeline (as round 5).
// ---------------------------------------------------------------------------
template <int Mv, int Nv, int Kv, int GBMv>
__device__ __forceinline__ void gemm_ps_body(const float* __restrict__ Ah,
                                             const float* __restrict__ Al,
                                             const float* __restrict__ Bh,
                                             const float* __restrict__ Bl,
                                             float* __restrict__ C) {
    constexpr int NT = (GBMv == 128) ? 8 : 4;
    constexpr int KT = Kv / 8;

    __shared__ __align__(16) float AsH[2][GBMv][12];
    __shared__ __align__(16) float AsL[2][GBMv][12];
    __shared__ __align__(16) float BsH[2][8][136];
    __shared__ __align__(16) float BsL[2][8][136];

    const int tid  = threadIdx.x;
    const int wid  = tid >> 5;
    const int lane = tid & 31;
    const int WM = (GBMv == 128) ? ((wid & 3) * 32) : ((wid & 1) * 32);
    const int WN = (GBMv == 128) ? ((wid >> 2) * 64) : ((wid >> 1) * 32);
    const int g = lane & 3;
    const int u = lane >> 2;
    const int row0 = blockIdx.y * GBMv;
    const int col0 = blockIdx.x * 128;

    const int am  = (GBMv == 128) ? (tid >> 1) : ((tid & 127) >> 1);
    const int ak4 = (tid & 1) * 4;
    const bool a_active = (GBMv == 128) || (tid < 128);
    const int bk  = tid >> 5;
    const int bn4 = (tid & 31) * 4;

    float acc[2][NT][4];
    #pragma unroll
    for (int mt = 0; mt < 2; mt++)
        #pragma unroll
        for (int nt = 0; nt < NT; nt++)
            #pragma unroll
            for (int q = 0; q < 4; q++) acc[mt][nt][q] = 0.f;

    auto prefetch = [&](int kt, int buf) {
        const int kbase = kt * 8;
        if (a_active) {
            int gm = row0 + am;
            bool p = (gm < Mv);
            int gmc = p ? gm : 0;
            uint32_t dh = (uint32_t)__cvta_generic_to_shared(&AsH[buf][am][ak4]);
            uint32_t dl = (uint32_t)__cvta_generic_to_shared(&AsL[buf][am][ak4]);
            cp_async16(dh, &Ah[(size_t)gmc * Kv + kbase + ak4], p);
            cp_async16(dl, &Al[(size_t)gmc * Kv + kbase + ak4], p);
        }
        {
            int gn = col0 + bn4;
            bool p = (gn < Nv);
            int gnc = p ? gn : 0;
            uint32_t dh = (uint32_t)__cvta_generic_to_shared(&BsH[buf][bk][bn4]);
            uint32_t dl = (uint32_t)__cvta_generic_to_shared(&BsL[buf][bk][bn4]);
            cp_async16(dh, &Bh[(size_t)(kbase + bk) * Nv + gnc], p);
            cp_async16(dl, &Bl[(size_t)(kbase + bk) * Nv + gnc], p);
        }
        cp_commit();
    };

    prefetch(0, 0);

    for (int kt = 0; kt < KT; kt++) {
        const int buf = kt & 1;
        if (kt + 1 < KT) {
            prefetch(kt + 1, buf ^ 1);
            cp_wait<1>();
        } else {
            cp_wait<0>();
        }
        __syncthreads();

        uint32_t ah[2][4], al[2][4], bh[NT][2], bl[NT][2];
        #pragma unroll
        for (int mt = 0; mt < 2; mt++) {
            int m0 = WM + mt * 16;
            ah[mt][0] = __float_as_uint(AsH[buf][m0 + u][g]);
            ah[mt][1] = __float_as_uint(AsH[buf][m0 + u + 8][g]);
            ah[mt][2] = __float_as_uint(AsH[buf][m0 + u][g + 4]);
            ah[mt][3] = __float_as_uint(AsH[buf][m0 + u + 8][g + 4]);
            al[mt][0] = __float_as_uint(AsL[buf][m0 + u][g]);
            al[mt][1] = __float_as_uint(AsL[buf][m0 + u + 8][g]);
            al[mt][2] = __float_as_uint(AsL[buf][m0 + u][g + 4]);
            al[mt][3] = __float_as_uint(AsL[buf][m0 + u + 8][g + 4]);
        }
        #pragma unroll
        for (int nt = 0; nt < NT; nt++) {
            int n0 = WN + nt * 8;
            bh[nt][0] = __float_as_uint(BsH[buf][g][n0 + u]);
            bh[nt][1] = __float_as_uint(BsH[buf][g + 4][n0 + u]);
            bl[nt][0] = __float_as_uint(BsL[buf][g][n0 + u]);
            bl[nt][1] = __float_as_uint(BsL[buf][g + 4][n0 + u]);
        }
        #pragma unroll
        for (int mt = 0; mt < 2; mt++)
            #pragma unroll
            for (int nt = 0; nt < NT; nt++) {
                mma_tf32(acc[mt][nt], ah[mt][0], ah[mt][1], ah[mt][2], ah[mt][3],
                         bh[nt][0], bh[nt][1]);
                mma_tf32(acc[mt][nt], ah[mt][0], ah[mt][1], ah[mt][2], ah[mt][3],
                         bl[nt][0], bl[nt][1]);
                mma_tf32(acc[mt][nt], al[mt][0], al[mt][1], al[mt][2], al[mt][3],
                         bh[nt][0], bh[nt][1]);
            }
        __syncthreads();
    }

    #pragma unroll
    for (int mt = 0; mt < 2; mt++) {
        int r0 = row0 + WM + mt * 16 + u;
        int r1 = r0 + 8;
        #pragma unroll
        for (int nt = 0; nt < NT; nt++) {
            int c = col0 + WN + nt * 8 + 2 * g;
            if (c < Nv) {
                if (r0 < Mv)
                    *(float2*)&C[(size_t)r0 * Nv + c] =
                        make_float2(acc[mt][nt][0], acc[mt][nt][1]);
                if (r1 < Mv)
                    *(float2*)&C[(size_t)r1 * Nv + c] =
                        make_float2(acc[mt][nt][2], acc[mt][nt][3]);
            }
        }
    }
}

__global__ void __launch_bounds__(256)
gemm1_kernel() {
    gemm_ps_body<NN, HID, IN_CH, 128>(g_xh, g_xl, g_w1h, g_w1l, g_h1);
}
__global__ void __launch_bounds__(256, 2)
gemm2_kernel() {
    gemm_ps_body<NN, OUT_CH, HID, 64>(g_o1h, g_o1l, g_w2h, g_w2l, g_h2);
}

// ---------------------------------------------------------------------------
// Attention coefficients
// ---------------------------------------------------------------------------
__global__ void attn1_kernel(const float* __restrict__ a_src,
                             const float* __restrict__ a_dst) {
    int n = blockIdx.x;
    __shared__ float row[HID];
    const float* hrow = &g_h1[(size_t)n * HID];
    for (int c = threadIdx.x; c < HID; c += blockDim.x) row[c] = hrow[c];
    __syncthreads();
    int t = threadIdx.x;
    if (t < 2 * H1) {
        int h = (t < H1) ? t : (t - H1);
        const float* a = (t < H1) ? a_src : a_dst;
        float s = 0.f;
        #pragma unroll
        for (int c = 0; c < C1; c++) s = fmaf(row[h * C1 + c], a[h * C1 + c], s);
        if (t < H1) g_as1[n * H1 + h] = s;
        else        g_ad1[n * H1 + h] = s;
    }
}

__global__ void attn2_kernel(const float* __restrict__ a_src,
                             const float* __restrict__ a_dst) {
    int warp = (blockIdx.x * blockDim.x + threadIdx.x) >> 5;
    int lane = threadIdx.x & 31;
    if (warp >= NN) return;
    const float* hrow = &g_h2[(size_t)warp * OUT_CH];
    float4 v  = *(const float4*)&hrow[lane * 4];
    float4 as = *(const float4*)&a_src[lane * 4];
    float4 ad = *(const float4*)&a_dst[lane * 4];
    float ss = v.x * as.x + v.y * as.y + v.z * as.z + v.w * as.w;
    float sd = v.x * ad.x + v.y * ad.y + v.z * ad.z + v.w * ad.w;
    #pragma unroll
    for (int o = 16; o; o >>= 1) {
        ss += __shfl_xor_sync(0xFFFFFFFFu, ss, o);
        sd += __shfl_xor_sync(0xFFFFFFFFu, sd, o);
    }
    if (lane == 0) { g_as2[warp] = ss; g_ad2[warp] = sd; }
}

// ---------------------------------------------------------------------------
// Layer-1 softmax stats: single-pass online max/sum per (node, head).
// 288 threads = 8 nodes x 36 heads per block. Branchless rescaling.
// ---------------------------------------------------------------------------
__global__ void __launch_bounds__(288)
stats1_kernel() {
    int node = blockIdx.x * 8 + threadIdx.x / H1;
    int h    = threadIdx.x % H1;
    if (node >= NN) return;
    float adn = g_ad1[node * H1 + h];
    int beg = g_rowptr[node];
    int end = g_rowptr[node + 1];
    float m = -1e30f, s = 0.f;
    for (int j = beg; j < end; j++) {
        int src = g_srt_src[j];
        float v = g_as1[src * H1 + h] + adn;
        v = (v > 0.f) ? v : 0.2f * v;
        float mn = fmaxf(m, v);
        s = s * __expf(m - mn) + __expf(v - mn);
        m = mn;
    }
    g_m1[node * H1 + h] = m;
    g_i1[node * H1 + h] = 1.0f / (s + 1e-16f);
}

// ---------------------------------------------------------------------------
// Layer-1 gather: 324 threads, thread t owns channels [4t, 4t+4) (float4).
// Chunks of 9 edges; weights computed once per (edge, head) into smem.
// Epilogue writes tf32 hi/lo split of relu(out + bias).
// ---------------------------------------------------------------------------
#define AGG1_T 324
#define CE1    9
__global__ void __launch_bounds__(AGG1_T)
agg1_kernel(const float* __restrict__ bias) {
    int n = blockIdx.x;
    int t = threadIdx.x;
    __shared__ float sm_m[H1], sm_inv[H1], sm_ad[H1];
    __shared__ float w[CE1][H1];
    __shared__ int   ssrc[CE1];

    if (t < H1)             sm_m[t]        = g_m1[n * H1 + t];
    else if (t < 2 * H1)    sm_inv[t - H1] = g_i1[n * H1 + (t - H1)];
    else if (t < 3 * H1)    sm_ad[t - 2*H1] = g_ad1[n * H1 + (t - 2*H1)];

    int beg = g_rowptr[n];
    int end = g_rowptr[n + 1];

    const int c0 = 4 * t;
    const int h0 = (c0 + 0) / C1;
    const int h1x = (c0 + 1) / C1;
    const int h2x = (c0 + 2) / C1;
    const int h3x = (c0 + 3) / C1;

    float4 acc = make_float4(0.f, 0.f, 0.f, 0.f);

    for (int j0 = beg; j0 < end; j0 += CE1) {
        int cnt = end - j0; if (cnt > CE1) cnt = CE1;
        if (t < cnt) ssrc[t] = g_srt_src[j0 + t];
        __syncthreads();
        if (t < cnt * H1) {
            int e = t / H1, h = t - e * H1;
            float v = g_as1[ssrc[e] * H1 + h] + sm_ad[h];
            v = (v > 0.f) ? v : 0.2f * v;
            w[e][h] = __expf(v - sm_m[h]) * sm_inv[h];
        }
        __syncthreads();
        for (int e = 0; e < cnt; e++) {
            float4 hv = *(const float4*)&g_h1[(size_t)ssrc[e] * HID + c0];
            acc.x = fmaf(hv.x, w[e][h0],  acc.x);
            acc.y = fmaf(hv.y, w[e][h1x], acc.y);
            acc.z = fmaf(hv.z, w[e][h2x], acc.z);
            acc.w = fmaf(hv.w, w[e][h3x], acc.w);
        }
        __syncthreads();
    }

    float4 b4 = *(const float4*)&bias[c0];
    float v0 = fmaxf(acc.x + b4.x, 0.f);
    float v1 = fmaxf(acc.y + b4.y, 0.f);
    float v2 = fmaxf(acc.z + b4.z, 0.f);
    float v3 = fmaxf(acc.w + b4.w, 0.f);
    float4 hi, lo;
    split_tf32(v0, hi.x, lo.x);
    split_tf32(v1, hi.y, lo.y);
    split_tf32(v2, hi.z, lo.z);
    split_tf32(v3, hi.w, lo.w);
    *(float4*)&g_o1h[(size_t)n * HID + c0] = hi;
    *(float4*)&g_o1l[(size_t)n * HID + c0] = lo;
}

// ---------------------------------------------------------------------------
// Layer-2 aggregation (1 head, 128 ch), fused softmax, chunked weights.
// ---------------------------------------------------------------------------
#define CE2 32
__global__ void __launch_bounds__(128)
agg2_kernel(const float* __restrict__ bias, float* __restrict__ out) {
    int n = blockIdx.x;
    int t = threadIdx.x;
    __shared__ float red[128];
    __shared__ float w2[CE2];
    __shared__ int   ssrc2[CE2];

    int beg = g_rowptr[n];
    int end = g_rowptr[n + 1];
    float adn = g_ad2[n];

    float lm = -1e30f;
    for (int j = beg + t; j < end; j += 128) {
        float v = g_as2[g_srt_src[j]] + adn;
        v = (v > 0.f) ? v : 0.2f * v;
        lm = fmaxf(lm, v);
    }
    red[t] = lm;
    __syncthreads();
    for (int o = 64; o; o >>= 1) {
        if (t < o) red[t] = fmaxf(red[t], red[t + o]);
        __syncthreads();
    }
    float m = red[0];
    __syncthreads();

    float ls = 0.f;
    for (int j = beg + t; j < end; j += 128) {
        float v = g_as2[g_srt_src[j]] + adn;
        v = (v > 0.f) ? v : 0.2f * v;
        ls += __expf(v - m);
    }
    red[t] = ls;
    __syncthreads();
    for (int o = 64; o; o >>= 1) {
        if (t < o) red[t] += red[t + o];
        __syncthreads();
    }
    float inv = 1.0f / (red[0] + 1e-16f);
    __syncthreads();

    float acc = 0.f;
    for (int j0 = beg; j0 < end; j0 += CE2) {
        int cnt = end - j0; if (cnt > CE2) cnt = CE2;
        if (t < cnt) {
            int s = g_srt_src[j0 + t];
            ssrc2[t] = s;
            float v = g_as2[s] + adn;
            v = (v > 0.f) ? v : 0.2f * v;
            w2[t] = __expf(v - m) * inv;
        }
        __syncthreads();
        for (int e = 0; e < cnt; e++)
            acc = fmaf(g_h2[(size_t)ssrc2[e] * OUT_CH + t], w2[e], acc);
        __syncthreads();
    }

    float v = acc + bias[t];
    out[(size_t)n * OUT_CH + t] = (v > 0.f) ? v : 0.f;
}

// ---------------------------------------------------------------------------
// Launch (ordered so gemm1 is launch #4 for the ncu window)
// ---------------------------------------------------------------------------
extern "C" void kernel_launch(void* const* d_in, const int* in_sizes, int n_in,
                              void* d_out, int out_size) {
    const float* x      = (const float*)d_in[0];
    const int*   ei     = (const int*)d_in[1];
    const float* W1     = (const float*)d_in[2];
    const float* a_src1 = (const float*)d_in[3];
    const float* a_dst1 = (const float*)d_in[4];
    const float* b1     = (const float*)d_in[5];
    const float* W2     = (const float*)d_in[6];
    const float* a_src2 = (const float*)d_in[7];
    const float* a_dst2 = (const float*)d_in[8];
    const float* b2     = (const float*)d_in[9];
    float*       out    = (float*)d_out;

    prep_kernel<<<512, 256>>>(x, W1, W2);                        // 1
    hist_kernel<<<(ETOT + 255) / 256, 256>>>(ei);                // 2
    scan_kernel<<<1, 1024>>>();                                  // 3
    {
        dim3 grid((HID + 127) / 128, (NN + 127) / 128);          // 4: gemm1
        gemm1_kernel<<<grid, 256>>>();
    }
    scatter_kernel<<<(ETOT + 255) / 256, 256>>>(ei);             // 5
    attn1_kernel<<<NN, 128>>>(a_src1, a_dst1);                   // 6
    stats1_kernel<<<(NN + 7) / 8, 288>>>();                      // 7
    agg1_kernel<<<NN, AGG1_T>>>(b1);                             // 8
    {
        dim3 grid(1, (NN + 63) / 64);                            // 9: gemm2
        gemm2_kernel<<<grid, 256>>>();
    }
    attn2_kernel<<<(NN * 32 + 255) / 256, 256>>>(a_src2, a_dst2);// 10
    agg2_kernel<<<NN, 128>>>(b2, out);                           // 11
}

// round 7
// speedup vs baseline: 2.0354x; 1.3923x over previous
#include <cuda_runtime.h>
#include <cuda_bf16.h>
#include <cstdint>

// ---------------------------------------------------------------------------
// Problem constants
// ---------------------------------------------------------------------------
#define NN      20000
#define EE      160000
#define ETOT    (EE + NN)
#define IN_CH   128
#define H1      36
#define C1      36
#define HID     (H1 * C1)   // 1296
#define OUT_CH  128
#define K1P     (IN_CH / 2)   // 64 pairs
#define K2P     (HID / 2)     // 648 pairs

// ---------------------------------------------------------------------------
// Device scratch
// ---------------------------------------------------------------------------
__device__ __align__(16) float g_h1[(size_t)NN * HID];     // x @ W1 (fp32)
__device__ __align__(16) float g_h2[(size_t)NN * OUT_CH];  // out1 @ W2 (fp32)
// bf16-pair packed operands (hi/lo split): pair = (elem 2k', elem 2k'+1)
__device__ __align__(16) unsigned int g_xph[(size_t)NN * K1P];
__device__ __align__(16) unsigned int g_xpl[(size_t)NN * K1P];
__device__ __align__(16) unsigned int g_w1ph[K1P * HID];
__device__ __align__(16) unsigned int g_w1pl[K1P * HID];
__device__ __align__(16) unsigned int g_w2ph[K2P * OUT_CH];
__device__ __align__(16) unsigned int g_w2pl[K2P * OUT_CH];
__device__ __align__(16) unsigned int g_o1ph[(size_t)NN * K2P];
__device__ __align__(16) unsigned int g_o1pl[(size_t)NN * K2P];
__device__ __align__(16) float g_as1[NN * H1];
__device__ __align__(16) float g_ad1[NN * H1];
__device__ __align__(16) float g_m1[NN * H1];
__device__ __align__(16) float g_i1[NN * H1];
__device__ __align__(16) float g_as2[NN];
__device__ __align__(16) float g_ad2[NN];
__device__ int g_hist[NN];
__device__ int g_rowptr[NN + 1];
__device__ int g_cursor[NN];
__device__ int g_srt_src[ETOT];

// ---------------------------------------------------------------------------
// bf16 split/pack helpers
// ---------------------------------------------------------------------------
__device__ __forceinline__ uint32_t pack_bf16(float a, float b) {
    __nv_bfloat162 t = __floats2bfloat162_rn(a, b);   // .x = a (low), .y = b
    return *reinterpret_cast<uint32_t*>(&t);
}
// split consecutive pair (v0, v1) into hi-pair / lo-pair
__device__ __forceinline__ void split2_bf16(float v0, float v1,
                                            uint32_t& ph, uint32_t& pl) {
    __nv_bfloat16 h0 = __float2bfloat16_rn(v0);
    __nv_bfloat16 h1 = __float2bfloat16_rn(v1);
    float r0 = v0 - __bfloat162float(h0);
    float r1 = v1 - __bfloat162float(h1);
    ph = pack_bf16(__bfloat162float(h0), __bfloat162float(h1));
    pl = pack_bf16(r0, r1);
}

__device__ __forceinline__ void mma_bf16(float* c,
                                         uint32_t a0, uint32_t a1,
                                         uint32_t a2, uint32_t a3,
                                         uint32_t b0, uint32_t b1) {
    asm volatile(
        "mma.sync.aligned.m16n8k16.row.col.f32.bf16.bf16.f32 "
        "{%0,%1,%2,%3}, {%4,%5,%6,%7}, {%8,%9}, {%0,%1,%2,%3};\n"
        : "+f"(c[0]), "+f"(c[1]), "+f"(c[2]), "+f"(c[3])
        : "r"(a0), "r"(a1), "r"(a2), "r"(a3), "r"(b0), "r"(b1));
}

__device__ __forceinline__ void cp_async16(uint32_t dst, const void* src, bool pred) {
    int sz = pred ? 16 : 0;
    asm volatile("cp.async.ca.shared.global [%0], [%1], 16, %2;\n"
                 :: "r"(dst), "l"(src), "r"(sz));
}
__device__ __forceinline__ void cp_commit() {
    asm volatile("cp.async.commit_group;\n");
}
template <int N>
__device__ __forceinline__ void cp_wait() {
    asm volatile("cp.async.wait_group %0;\n" :: "n"(N));
}

// ---------------------------------------------------------------------------
// prep: bf16 pair-pack x/W1/W2 (hi+lo) + zero hist
// ---------------------------------------------------------------------------
__global__ void prep_kernel(const float* __restrict__ x,
                            const float* __restrict__ W1,
                            const float* __restrict__ W2) {
    int stride = gridDim.x * blockDim.x;
    int tid0 = blockIdx.x * blockDim.x + threadIdx.x;
    const float2* x2 = (const float2*)x;
    for (int i = tid0; i < NN * K1P; i += stride) {
        float2 v = x2[i];
        uint32_t ph, pl;
        split2_bf16(v.x, v.y, ph, pl);
        g_xph[i] = ph; g_xpl[i] = pl;
    }
    for (int i = tid0; i < K1P * HID; i += stride) {
        int kp = i / HID, n = i - kp * HID;
        uint32_t ph, pl;
        split2_bf16(W1[(2 * kp) * HID + n], W1[(2 * kp + 1) * HID + n], ph, pl);
        g_w1ph[i] = ph; g_w1pl[i] = pl;
    }
    for (int i = tid0; i < K2P * OUT_CH; i += stride) {
        int kp = i / OUT_CH, n = i - kp * OUT_CH;
        uint32_t ph, pl;
        split2_bf16(W2[(2 * kp) * OUT_CH + n], W2[(2 * kp + 1) * OUT_CH + n], ph, pl);
        g_w2ph[i] = ph; g_w2pl[i] = pl;
    }
    for (int i = tid0; i < NN; i += stride) g_hist[i] = 0;
}

// ---------------------------------------------------------------------------
// Edge helpers
// ---------------------------------------------------------------------------
__device__ __forceinline__ int edge_src(const int* __restrict__ ei, int j) {
    return (j < EE) ? ei[j] : (j - EE);
}
__device__ __forceinline__ int edge_dst(const int* __restrict__ ei, int j) {
    return (j < EE) ? ei[EE + j] : (j - EE);
}

// ---------------------------------------------------------------------------
// CSR build
// ---------------------------------------------------------------------------
__global__ void hist_kernel(const int* __restrict__ ei) {
    int j = blockIdx.x * blockDim.x + threadIdx.x;
    if (j < ETOT) atomicAdd(&g_hist[edge_dst(ei, j)], 1);
}
__global__ void scan_kernel() {
    __shared__ int sdata[1024];
    int t = threadIdx.x;
    if (t == 0) g_rowptr[0] = 0;
    int offset = 0;
    for (int base = 0; base < NN; base += 1024) {
        int v = (base + t < NN) ? g_hist[base + t] : 0;
        sdata[t] = v;
        __syncthreads();
        for (int d = 1; d < 1024; d <<= 1) {
            int add = (t >= d) ? sdata[t - d] : 0;
            __syncthreads();
            sdata[t] += add;
            __syncthreads();
        }
        int incl = sdata[t];
        if (base + t < NN) {
            g_rowptr[base + t + 1] = offset + incl;
            g_cursor[base + t]     = offset + incl - v;
        }
        offset += sdata[1023];
        __syncthreads();
    }
}
__global__ void scatter_kernel(const int* __restrict__ ei) {
    int j = blockIdx.x * blockDim.x + threadIdx.x;
    if (j >= ETOT) return;
    int d = edge_dst(ei, j);
    int pos = atomicAdd(&g_cursor[d], 1);
    g_srt_src[pos] = edge_src(ei, j);
}

// ---------------------------------------------------------------------------
// bf16-split GEMM (3x m16n8k16): C = (Ah+Al)(Bh+Bl) ~= AhBh + AhBl + AlBh
// Operands pre-packed as uint32 bf16-pairs along k.
// Block 256 threads / 8 warps; k-tile = 16 elements = 8 pairs.
// A smem [m][12] pairs (stride 12, conflict-free); B smem [k'][136].
// Fragment indexing identical to the tf32 variant (verified bijection).
// ---------------------------------------------------------------------------
template <int Mv, int Nv, int Kv, int GBMv>
__device__ __forceinline__ void gemm_bf_body(const unsigned int* __restrict__ Ah,
                                             const unsigned int* __restrict__ Al,
                                             const unsigned int* __restrict__ Bh,
                                             const unsigned int* __restrict__ Bl,
                                             float* __restrict__ C) {
    constexpr int NT = (GBMv == 128) ? 8 : 4;
    constexpr int KT = Kv / 16;      // k-tiles of 16 elements (8 pairs)
    constexpr int KP = Kv / 2;       // pairs per row of A

    __shared__ __align__(16) unsigned int AsH[2][GBMv][12];
    __shared__ __align__(16) unsigned int AsL[2][GBMv][12];
    __shared__ __align__(16) unsigned int BsH[2][8][136];
    __shared__ __align__(16) unsigned int BsL[2][8][136];

    const int tid  = threadIdx.x;
    const int wid  = tid >> 5;
    const int lane = tid & 31;
    const int WM = (GBMv == 128) ? ((wid & 3) * 32) : ((wid & 1) * 32);
    const int WN = (GBMv == 128) ? ((wid >> 2) * 64) : ((wid >> 1) * 32);
    const int g = lane & 3;
    const int u = lane >> 2;
    const int row0 = blockIdx.y * GBMv;
    const int col0 = blockIdx.x * 128;

    const int am  = (GBMv == 128) ? (tid >> 1) : ((tid & 127) >> 1);
    const int ak4 = (tid & 1) * 4;                 // pair offset 0 / 4
    const bool a_active = (GBMv == 128) || (tid < 128);
    const int bk  = tid >> 5;                      // 0..7 (pair row)
    const int bn4 = (tid & 31) * 4;

    float acc[2][NT][4];
    #pragma unroll
    for (int mt = 0; mt < 2; mt++)
        #pragma unroll
        for (int nt = 0; nt < NT; nt++)
            #pragma unroll
            for (int q = 0; q < 4; q++) acc[mt][nt][q] = 0.f;

    auto prefetch = [&](int kt, int buf) {
        const int kp0 = kt * 8;                    // pair base
        if (a_active) {
            int gm = row0 + am;
            bool p = (gm < Mv);
            int gmc = p ? gm : 0;
            uint32_t dh = (uint32_t)__cvta_generic_to_shared(&AsH[buf][am][ak4]);
            uint32_t dl = (uint32_t)__cvta_generic_to_shared(&AsL[buf][am][ak4]);
            cp_async16(dh, &Ah[(size_t)gmc * KP + kp0 + ak4], p);
            cp_async16(dl, &Al[(size_t)gmc * KP + kp0 + ak4], p);
        }
        {
            int gn = col0 + bn4;
            bool p = (gn < Nv);
            int gnc = p ? gn : 0;
            uint32_t dh = (uint32_t)__cvta_generic_to_shared(&BsH[buf][bk][bn4]);
            uint32_t dl = (uint32_t)__cvta_generic_to_shared(&BsL[buf][bk][bn4]);
            cp_async16(dh, &Bh[(size_t)(kp0 + bk) * Nv + gnc], p);
            cp_async16(dl, &Bl[(size_t)(kp0 + bk) * Nv + gnc], p);
        }
        cp_commit();
    };

    prefetch(0, 0);

    for (int kt = 0; kt < KT; kt++) {
        const int buf = kt & 1;
        if (kt + 1 < KT) {
            prefetch(kt + 1, buf ^ 1);
            cp_wait<1>();
        } else {
            cp_wait<0>();
        }
        __syncthreads();

        uint32_t ah[2][4], al[2][4], bh[NT][2], bl[NT][2];
        #pragma unroll
        for (int mt = 0; mt < 2; mt++) {
            int m0 = WM + mt * 16;
            ah[mt][0] = AsH[buf][m0 + u][g];
            ah[mt][1] = AsH[buf][m0 + u + 8][g];
            ah[mt][2] = AsH[buf][m0 + u][g + 4];
            ah[mt][3] = AsH[buf][m0 + u + 8][g + 4];
            al[mt][0] = AsL[buf][m0 + u][g];
            al[mt][1] = AsL[buf][m0 + u + 8][g];
            al[mt][2] = AsL[buf][m0 + u][g + 4];
            al[mt][3] = AsL[buf][m0 + u + 8][g + 4];
        }
        #pragma unroll
        for (int nt = 0; nt < NT; nt++) {
            int n0 = WN + nt * 8;
            bh[nt][0] = BsH[buf][g][n0 + u];
            bh[nt][1] = BsH[buf][g + 4][n0 + u];
            bl[nt][0] = BsL[buf][g][n0 + u];
            bl[nt][1] = BsL[buf][g + 4][n0 + u];
        }
        #pragma unroll
        for (int mt = 0; mt < 2; mt++)
            #pragma unroll
            for (int nt = 0; nt < NT; nt++) {
                mma_bf16(acc[mt][nt], ah[mt][0], ah[mt][1], ah[mt][2], ah[mt][3],
                         bh[nt][0], bh[nt][1]);
                mma_bf16(acc[mt][nt], ah[mt][0], ah[mt][1], ah[mt][2], ah[mt][3],
                         bl[nt][0], bl[nt][1]);
                mma_bf16(acc[mt][nt], al[mt][0], al[mt][1], al[mt][2], al[mt][3],
                         bh[nt][0], bh[nt][1]);
            }
        __syncthreads();
    }

    #pragma unroll
    for (int mt = 0; mt < 2; mt++) {
        int r0 = row0 + WM + mt * 16 + u;
        int r1 = r0 + 8;
        #pragma unroll
        for (int nt = 0; nt < NT; nt++) {
            int c = col0 + WN + nt * 8 + 2 * g;
            if (c < Nv) {
                if (r0 < Mv)
                    *(float2*)&C[(size_t)r0 * Nv + c] =
                        make_float2(acc[mt][nt][0], acc[mt][nt][1]);
                if (r1 < Mv)
                    *(float2*)&C[(size_t)r1 * Nv + c] =
                        make_float2(acc[mt][nt][2], acc[mt][nt][3]);
            }
        }
    }
}

__global__ void __launch_bounds__(256)
gemm1_kernel() {
    gemm_bf_body<NN, HID, IN_CH, 128>(g_xph, g_xpl, g_w1ph, g_w1pl, g_h1);
}
__global__ void __launch_bounds__(256, 2)
gemm2_kernel() {
    gemm_bf_body<NN, OUT_CH, HID, 64>(g_o1ph, g_o1pl, g_w2ph, g_w2pl, g_h2);
}

// ---------------------------------------------------------------------------
// Attention coefficients
// ---------------------------------------------------------------------------
__global__ void attn1_kernel(const float* __restrict__ a_src,
                             const float* __restrict__ a_dst) {
    int n = blockIdx.x;
    __shared__ float row[HID];
    const float* hrow = &g_h1[(size_t)n * HID];
    for (int c = threadIdx.x; c < HID; c += blockDim.x) row[c] = hrow[c];
    __syncthreads();
    int t = threadIdx.x;
    if (t < 2 * H1) {
        int h = (t < H1) ? t : (t - H1);
        const float* a = (t < H1) ? a_src : a_dst;
        float s = 0.f;
        #pragma unroll
        for (int c = 0; c < C1; c++) s = fmaf(row[h * C1 + c], a[h * C1 + c], s);
        if (t < H1) g_as1[n * H1 + h] = s;
        else        g_ad1[n * H1 + h] = s;
    }
}

__global__ void attn2_kernel(const float* __restrict__ a_src,
                             const float* __restrict__ a_dst) {
    int warp = (blockIdx.x * blockDim.x + threadIdx.x) >> 5;
    int lane = threadIdx.x & 31;
    if (warp >= NN) return;
    const float* hrow = &g_h2[(size_t)warp * OUT_CH];
    float4 v  = *(const float4*)&hrow[lane * 4];
    float4 as = *(const float4*)&a_src[lane * 4];
    float4 ad = *(const float4*)&a_dst[lane * 4];
    float ss = v.x * as.x + v.y * as.y + v.z * as.z + v.w * as.w;
    float sd = v.x * ad.x + v.y * ad.y + v.z * ad.z + v.w * ad.w;
    #pragma unroll
    for (int o = 16; o; o >>= 1) {
        ss += __shfl_xor_sync(0xFFFFFFFFu, ss, o);
        sd += __shfl_xor_sync(0xFFFFFFFFu, sd, o);
    }
    if (lane == 0) { g_as2[warp] = ss; g_ad2[warp] = sd; }
}

// ---------------------------------------------------------------------------
// Layer-1 softmax stats: single-pass online max/sum per (node, head).
// ---------------------------------------------------------------------------
__global__ void __launch_bounds__(288)
stats1_kernel() {
    int node = blockIdx.x * 8 + threadIdx.x / H1;
    int h    = threadIdx.x % H1;
    if (node >= NN) return;
    float adn = g_ad1[node * H1 + h];
    int beg = g_rowptr[node];
    int end = g_rowptr[node + 1];
    float m = -1e30f, s = 0.f;
    for (int j = beg; j < end; j++) {
        int src = g_srt_src[j];
        float v = g_as1[src * H1 + h] + adn;
        v = (v > 0.f) ? v : 0.2f * v;
        float mn = fmaxf(m, v);
        s = s * __expf(m - mn) + __expf(v - mn);
        m = mn;
    }
    g_m1[node * H1 + h] = m;
    g_i1[node * H1 + h] = 1.0f / (s + 1e-16f);
}

// ---------------------------------------------------------------------------
// Layer-1 gather: 324 threads, thread t owns channels [4t, 4t+4) (float4).
// Epilogue writes packed bf16-pair hi/lo of relu(out + bias) for gemm2.
// ---------------------------------------------------------------------------
#define AGG1_T 324
#define CE1    9
__global__ void __launch_bounds__(AGG1_T)
agg1_kernel(const float* __restrict__ bias) {
    int n = blockIdx.x;
    int t = threadIdx.x;
    __shared__ float sm_m[H1], sm_inv[H1], sm_ad[H1];
    __shared__ float w[CE1][H1];
    __shared__ int   ssrc[CE1];

    if (t < H1)             sm_m[t]        = g_m1[n * H1 + t];
    else if (t < 2 * H1)    sm_inv[t - H1] = g_i1[n * H1 + (t - H1)];
    else if (t < 3 * H1)    sm_ad[t - 2*H1] = g_ad1[n * H1 + (t - 2*H1)];

    int beg = g_rowptr[n];
    int end = g_rowptr[n + 1];

    const int c0 = 4 * t;
    const int h0 = (c0 + 0) / C1;
    const int h1x = (c0 + 1) / C1;
    const int h2x = (c0 + 2) / C1;
    const int h3x = (c0 + 3) / C1;

    float4 acc = make_float4(0.f, 0.f, 0.f, 0.f);

    for (int j0 = beg; j0 < end; j0 += CE1) {
        int cnt = end - j0; if (cnt > CE1) cnt = CE1;
        if (t < cnt) ssrc[t] = g_srt_src[j0 + t];
        __syncthreads();
        if (t < cnt * H1) {
            int e = t / H1, h = t - e * H1;
            float v = g_as1[ssrc[e] * H1 + h] + sm_ad[h];
            v = (v > 0.f) ? v : 0.2f * v;
            w[e][h] = __expf(v - sm_m[h]) * sm_inv[h];
        }
        __syncthreads();
        for (int e = 0; e < cnt; e++) {
            float4 hv = *(const float4*)&g_h1[(size_t)ssrc[e] * HID + c0];
            acc.x = fmaf(hv.x, w[e][h0],  acc.x);
            acc.y = fmaf(hv.y, w[e][h1x], acc.y);
            acc.z = fmaf(hv.z, w[e][h2x], acc.z);
            acc.w = fmaf(hv.w, w[e][h3x], acc.w);
        }
        __syncthreads();
    }

    float4 b4 = *(const float4*)&bias[c0];
    float v0 = fmaxf(acc.x + b4.x, 0.f);
    float v1 = fmaxf(acc.y + b4.y, 0.f);
    float v2 = fmaxf(acc.z + b4.z, 0.f);
    float v3 = fmaxf(acc.w + b4.w, 0.f);
    uint32_t ph0, pl0, ph1, pl1;
    split2_bf16(v0, v1, ph0, pl0);
    split2_bf16(v2, v3, ph1, pl1);
    *(uint2*)&g_o1ph[(size_t)n * K2P + 2 * t] = make_uint2(ph0, ph1);
    *(uint2*)&g_o1pl[(size_t)n * K2P + 2 * t] = make_uint2(pl0, pl1);
}

// ---------------------------------------------------------------------------
// Layer-2 aggregation (1 head, 128 ch), fused softmax, chunked weights.
// ---------------------------------------------------------------------------
#define CE2 32
__global__ void __launch_bounds__(128)
agg2_kernel(const float* __restrict__ bias, float* __restrict__ out) {
    int n = blockIdx.x;
    int t = threadIdx.x;
    __shared__ float red[128];
    __shared__ float w2[CE2];
    __shared__ int   ssrc2[CE2];

    int beg = g_rowptr[n];
    int end = g_rowptr[n + 1];
    float adn = g_ad2[n];

    float lm = -1e30f;
    for (int j = beg + t; j < end; j += 128) {
        float v = g_as2[g_srt_src[j]] + adn;
        v = (v > 0.f) ? v : 0.2f * v;
        lm = fmaxf(lm, v);
    }
    red[t] = lm;
    __syncthreads();
    for (int o = 64; o; o >>= 1) {
        if (t < o) red[t] = fmaxf(red[t], red[t + o]);
        __syncthreads();
    }
    float m = red[0];
    __syncthreads();

    float ls = 0.f;
    for (int j = beg + t; j < end; j += 128) {
        float v = g_as2[g_srt_src[j]] + adn;
        v = (v > 0.f) ? v : 0.2f * v;
        ls += __expf(v - m);
    }
    red[t] = ls;
    __syncthreads();
    for (int o = 64; o; o >>= 1) {
        if (t < o) red[t] += red[t + o];
        __syncthreads();
    }
    float inv = 1.0f / (red[0] + 1e-16f);
    __syncthreads();

    float acc = 0.f;
    for (int j0 = beg; j0 < end; j0 += CE2) {
        int cnt = end - j0; if (cnt > CE2) cnt = CE2;
        if (t < cnt) {
            int s = g_srt_src[j0 + t];
            ssrc2[t] = s;
            float v = g_as2[s] + adn;
            v = (v > 0.f) ? v : 0.2f * v;
            w2[t] = __expf(v - m) * inv;
        }
        __syncthreads();
        for (int e = 0; e < cnt; e++)
            acc = fmaf(g_h2[(size_t)ssrc2[e] * OUT_CH + t], w2[e], acc);
        __syncthreads();
    }

    float v = acc + bias[t];
    out[(size_t)n * OUT_CH + t] = (v > 0.f) ? v : 0.f;
}

// ---------------------------------------------------------------------------
// Launch (gemm1 kept at slot #4 for the ncu window)
// ---------------------------------------------------------------------------
extern "C" void kernel_launch(void* const* d_in, const int* in_sizes, int n_in,
                              void* d_out, int out_size) {
    const float* x      = (const float*)d_in[0];
    const int*   ei     = (const int*)d_in[1];
    const float* W1     = (const float*)d_in[2];
    const float* a_src1 = (const float*)d_in[3];
    const float* a_dst1 = (const float*)d_in[4];
    const float* b1     = (const float*)d_in[5];
    const float* W2     = (const float*)d_in[6];
    const float* a_src2 = (const float*)d_in[7];
    const float* a_dst2 = (const float*)d_in[8];
    const float* b2     = (const float*)d_in[9];
    float*       out    = (float*)d_out;

    prep_kernel<<<512, 256>>>(x, W1, W2);                        // 1
    hist_kernel<<<(ETOT + 255) / 256, 256>>>(ei);                // 2
    scan_kernel<<<1, 1024>>>();                                  // 3
    {
        dim3 grid((HID + 127) / 128, (NN + 127) / 128);          // 4: gemm1
        gemm1_kernel<<<grid, 256>>>();
    }
    scatter_kernel<<<(ETOT + 255) / 256, 256>>>(ei);             // 5
    attn1_kernel<<<NN, 128>>>(a_src1, a_dst1);                   // 6
    stats1_kernel<<<(NN + 7) / 8, 288>>>();                      // 7
    agg1_kernel<<<NN, AGG1_T>>>(b1);                             // 8
    {
        dim3 grid(1, (NN + 63) / 64);                            // 9: gemm2
        gemm2_kernel<<<grid, 256>>>();
    }
    attn2_kernel<<<(NN * 32 + 255) / 256, 256>>>(a_src2, a_dst2);// 10
    agg2_kernel<<<NN, 128>>>(b2, out);                           // 11
}